// round 11
// baseline (speedup 1.0000x reference)
#include <cuda_runtime.h>
#include <cuda_fp16.h>
#include <math.h>
#include <stdint.h>

// Problem constants
#define BATCH   8192
#define DMODEL  1024
#define DFF     4096
#define KPATH   4
#define RANK    16
#define HD      512
#define KCAT    (KPATH * DFF)          // 16384

// ---------------- scratch (device globals; no allocation allowed) ----------
__device__ __half g_W1h[KPATH * DFF * DMODEL];   // [k][4096][1024] (N,K) 32MB
__device__ __half g_W2n[KPATH * DFF * DMODEL];   // [k][4096][1024] natural 32MB
__device__ __half g_Wf[HD * KCAT];               // [512][16384] = concat_k Wf_k 16MB
__device__ __half g_hdinTh[HD * DMODEL];
__device__ __half g_hdoutTh[DMODEL * HD];
__device__ __half g_xh[BATCH * DMODEL];          // 16MB
__device__ __half g_hall[(size_t)BATCH * KCAT];  // [8192][16384] 256MB
__device__ __half g_colh[BATCH * HD];            // 8MB
__device__ float  g_S[DMODEL * KPATH];           // routing mat [1024][4]
__device__ float  g_probs[BATCH * KPATH];

// ---------------- builders / converters -------------------------------------
__global__ void build_w1h(const float* __restrict__ c1a, const float* __restrict__ c1b) {
    int idx = blockIdx.x * blockDim.x + threadIdx.x;
    if (idx >= KPATH * DFF * DMODEL) return;
    int d  = idx & (DMODEL - 1);
    int t  = idx >> 10;
    int nn = t & (DFF - 1);
    int k  = t >> 12;
    int m = d >> 5, p = d & 31;
    int n = nn >> 6, o = nn & 63;
    const float* a = c1a + (((k * 32 + m) * 64 + n) * 16);
    const float* b = c1b + ((size_t)(k * 16) * 32 + p) * 64 + o;
    float s = 0.f;
#pragma unroll
    for (int r = 0; r < RANK; r++) s += a[r] * b[(size_t)r * 32 * 64];
    g_W1h[idx] = __float2half(s);
}

__global__ void build_w2n(const float* __restrict__ c2a, const float* __restrict__ c2b) {
    int idx = blockIdx.x * blockDim.x + threadIdx.x;
    if (idx >= KPATH * DFF * DMODEL) return;
    int dm = idx & (DMODEL - 1);
    int t  = idx >> 10;
    int ff = t & (DFF - 1);
    int k  = t >> 12;
    int n = dm >> 5, o = dm & 31;
    int m = ff >> 6, p = ff & 63;
    const float* a = c2a + (((k * 64 + m) * 32 + n) * 16);
    const float* b = c2b + ((size_t)(k * 16) * 64 + p) * 32 + o;
    float s = 0.f;
#pragma unroll
    for (int r = 0; r < RANK; r++) s += a[r] * b[(size_t)r * 64 * 32];
    g_W2n[idx] = __float2half(s);
}

__global__ void conv_x(const float* __restrict__ x) {
    int i = blockIdx.x * blockDim.x + threadIdx.x;
    if (i < BATCH * DMODEL) g_xh[i] = __float2half(x[i]);
}
__global__ void transpose_hdin(const float* __restrict__ hd_in) {
    int i = blockIdx.x * blockDim.x + threadIdx.x;
    if (i >= DMODEL * HD) return;
    int d = i / HD, h2 = i % HD;
    g_hdinTh[(size_t)h2 * DMODEL + d] = __float2half(hd_in[i]);
}
__global__ void transpose_hdout(const float* __restrict__ hd_out) {
    int i = blockIdx.x * blockDim.x + threadIdx.x;
    if (i >= HD * DMODEL) return;
    int h2 = i / DMODEL, d = i % DMODEL;
    g_hdoutTh[(size_t)d * HD + h2] = __float2half(hd_out[i]);
}

// S[d][k] = sum_h hd_in[d,h] * pb[k,h]   (folds hd_in into routing)
__global__ void build_S(const float* __restrict__ hd_in, const float* __restrict__ pb) {
    int gid  = blockIdx.x * blockDim.x + threadIdx.x;
    int d    = gid >> 5;
    int lane = gid & 31;
    if (d >= DMODEL) return;
    const float* hr = hd_in + (size_t)d * HD;
    float s0 = 0.f, s1 = 0.f, s2 = 0.f, s3 = 0.f;
    for (int h = lane; h < HD; h += 32) {
        float v = hr[h];
        s0 += v * pb[0 * HD + h];
        s1 += v * pb[1 * HD + h];
        s2 += v * pb[2 * HD + h];
        s3 += v * pb[3 * HD + h];
    }
#pragma unroll
    for (int off = 16; off; off >>= 1) {
        s0 += __shfl_xor_sync(0xffffffffu, s0, off);
        s1 += __shfl_xor_sync(0xffffffffu, s1, off);
        s2 += __shfl_xor_sync(0xffffffffu, s2, off);
        s3 += __shfl_xor_sync(0xffffffffu, s3, off);
    }
    if (lane == 0) {
        g_S[d * 4 + 0] = s0; g_S[d * 4 + 1] = s1;
        g_S[d * 4 + 2] = s2; g_S[d * 4 + 3] = s3;
    }
}

// probs[b,:] = softmax(x[b,:] @ S)
__global__ void routing_kernel(const float* __restrict__ x) {
    int gid  = blockIdx.x * blockDim.x + threadIdx.x;
    int b    = gid >> 5;
    int lane = gid & 31;
    if (b >= BATCH) return;
    const float* xr = x + (size_t)b * DMODEL;
    float s0 = 0.f, s1 = 0.f, s2 = 0.f, s3 = 0.f;
    for (int d = lane; d < DMODEL; d += 32) {
        float v = xr[d];
        float4 S4 = *(const float4*)&g_S[d * 4];
        s0 += v * S4.x; s1 += v * S4.y; s2 += v * S4.z; s3 += v * S4.w;
    }
#pragma unroll
    for (int off = 16; off; off >>= 1) {
        s0 += __shfl_xor_sync(0xffffffffu, s0, off);
        s1 += __shfl_xor_sync(0xffffffffu, s1, off);
        s2 += __shfl_xor_sync(0xffffffffu, s2, off);
        s3 += __shfl_xor_sync(0xffffffffu, s3, off);
    }
    if (lane == 0) {
        float mx = fmaxf(fmaxf(s0, s1), fmaxf(s2, s3));
        float e0 = expf(s0 - mx), e1 = expf(s1 - mx);
        float e2 = expf(s2 - mx), e3 = expf(s3 - mx);
        float inv = 1.0f / (e0 + e1 + e2 + e3);
        g_probs[b * 4 + 0] = e0 * inv;
        g_probs[b * 4 + 1] = e1 * inv;
        g_probs[b * 4 + 2] = e2 * inv;
        g_probs[b * 4 + 3] = e3 * inv;
    }
}

// ---------------- fp16 mma.sync m16n8k16 GEMM, z-batched -------------------
// CTA 128x128, BK=64, SW128, 3 stages. 128 threads = 4 warps (2x2), warp 64x64.
#define BM 128
#define BN 128
#define BK 64
#define STAGES 3
#define TILEB (BM * 128)
#define STAGEB (2 * TILEB)
#define GEMM_SMEM (STAGES * STAGEB)    // 98304
#define NT 128

__device__ __forceinline__ void cp16(uint32_t dst, const void* src) {
    asm volatile("cp.async.cg.shared.global [%0], [%1], 16;"
                 :: "r"(dst), "l"(src) : "memory");
}
__device__ __forceinline__ void cp_commit() {
    asm volatile("cp.async.commit_group;" ::: "memory");
}
template <int N>
__device__ __forceinline__ void cp_wait() {
    asm volatile("cp.async.wait_group %0;" :: "n"(N) : "memory");
}
__device__ __forceinline__ void ldsm4(uint32_t* r, uint32_t addr) {
    asm volatile("ldmatrix.sync.aligned.m8n8.x4.shared.b16 {%0,%1,%2,%3}, [%4];"
                 : "=r"(r[0]), "=r"(r[1]), "=r"(r[2]), "=r"(r[3]) : "r"(addr));
}
__device__ __forceinline__ void mma16816(float* c, const uint32_t* a, const uint32_t* b) {
    asm volatile(
        "mma.sync.aligned.m16n8k16.row.col.f32.f16.f16.f32 "
        "{%0,%1,%2,%3}, {%4,%5,%6,%7}, {%8,%9}, {%0,%1,%2,%3};"
        : "+f"(c[0]), "+f"(c[1]), "+f"(c[2]), "+f"(c[3])
        : "r"(a[0]), "r"(a[1]), "r"(a[2]), "r"(a[3]), "r"(b[0]), "r"(b[1]));
}

__device__ __forceinline__ float gelu_f(float v) {
    float u = 1.5957691216057308f * (v + 0.044715f * v * v * v);
    return v * (1.0f / (1.0f + __expf(-u)));
}

// EPI: 0 = plain, 1 = probs*gelu -> half, 3 = pw-row-scale -> half
// Cs = output row stride (elements); scz = output column offset per z slice.
template <int EPI, typename OutT>
__global__ __launch_bounds__(NT, 2)
void tgemm(const __half* __restrict__ A, const __half* __restrict__ Bt,
           OutT* __restrict__ C, int M, int N, int Kd, int Cs,
           const float* __restrict__ pw,
           size_t saz, size_t sbz, size_t scz)
{
    extern __shared__ char smem[];
    uint32_t sbase = (uint32_t)__cvta_generic_to_shared(smem);

    int tid  = threadIdx.x;
    int wid  = tid >> 5;
    int lane = tid & 31;
    int g    = lane >> 2;
    int tig  = lane & 3;
    int wm   = wid & 1;        // 2 warps in M, 64 rows each
    int wn   = wid >> 1;       // 2 warps in N, 64 cols each
    int kz   = blockIdx.z;

    const __half* Ab = A  + (size_t)kz * saz + (size_t)blockIdx.y * BM * Kd;
    const __half* Bb = Bt + (size_t)kz * sbz + (size_t)blockIdx.x * BN * Kd;
    OutT* Cb = C + (size_t)kz * scz;
    int KT = Kd / BK;

    float acc[4][8][4];
#pragma unroll
    for (int i = 0; i < 4; i++)
#pragma unroll
        for (int j = 0; j < 8; j++)
#pragma unroll
            for (int q = 0; q < 4; q++) acc[i][j][q] = 0.f;

    uint32_t xm      = (uint32_t)(lane & 7) << 4;
    uint32_t a_row   = (uint32_t)(wm * 64 + (lane & 15)) * 128;
    uint32_t a_klane = (uint32_t)((lane >> 1) & 8) * 2;
    int nlo          = (lane & 7) | ((lane & 16) >> 1);
    uint32_t b_klane = (uint32_t)(lane & 8) * 2;

    auto load_stage = [&](int stage, int kt) {
        uint32_t abase = sbase + stage * STAGEB;
        uint32_t bbase = abase + TILEB;
        const __half* As = Ab + (size_t)kt * BK;
        const __half* Bs = Bb + (size_t)kt * BK;
#pragma unroll
        for (int i = 0; i < 8; i++) {
            int c   = tid + NT * i;       // 0..1023
            int row = c >> 3;
            int ch  = c & 7;
            uint32_t off = (uint32_t)row * 128 + (uint32_t)ch * 16;
            uint32_t sw  = off ^ ((off >> 3) & 0x70);
            cp16(abase + sw, As + (size_t)row * Kd + ch * 8);
            cp16(bbase + sw, Bs + (size_t)row * Kd + ch * 8);
        }
    };

#pragma unroll
    for (int s = 0; s < STAGES - 1; s++) {
        if (s < KT) load_stage(s, s);
        cp_commit();
    }

    for (int kt = 0; kt < KT; kt++) {
        cp_wait<STAGES - 2>();
        __syncthreads();

        int nxt = kt + STAGES - 1;
        if (nxt < KT) load_stage(nxt % STAGES, nxt);
        cp_commit();

        uint32_t abase = sbase + (kt % STAGES) * STAGEB;
        uint32_t bbase = abase + TILEB;

#pragma unroll
        for (int ks = 0; ks < 4; ks++) {
            uint32_t kb = (uint32_t)ks * 32;
            uint32_t af[4][4];
#pragma unroll
            for (int mf = 0; mf < 4; mf++)
                ldsm4(af[mf], abase + a_row + (uint32_t)mf * 16 * 128 +
                                ((kb + a_klane) ^ xm));
            uint32_t bf[4][4];
#pragma unroll
            for (int ng = 0; ng < 4; ng++)
                ldsm4(bf[ng], bbase + (uint32_t)(wn * 64 + ng * 16 + nlo) * 128 +
                                ((kb + b_klane) ^ xm));
#pragma unroll
            for (int mf = 0; mf < 4; mf++)
#pragma unroll
                for (int ng = 0; ng < 4; ng++) {
                    mma16816(acc[mf][2 * ng + 0], af[mf], &bf[ng][0]);
                    mma16816(acc[mf][2 * ng + 1], af[mf], &bf[ng][2]);
                }
        }
        __syncthreads();
    }

    // ---- epilogue ----
#pragma unroll
    for (int mf = 0; mf < 4; mf++) {
        int row0 = blockIdx.y * BM + wm * 64 + mf * 16 + g;
#pragma unroll
        for (int half = 0; half < 2; half++) {
            int row = row0 + half * 8;
            float rs = 1.f;
            if (EPI == 1) rs = g_probs[row * KPATH + kz];
            if (EPI == 3) rs = pw[kz * HD + row];
            OutT* Crow = Cb + (size_t)row * Cs;
#pragma unroll
            for (int nf = 0; nf < 8; nf++) {
                int col = blockIdx.x * BN + wn * 64 + (nf >> 1) * 16 + (nf & 1) * 8 + 2 * tig;
                float v0 = acc[mf][nf][half * 2 + 0];
                float v1 = acc[mf][nf][half * 2 + 1];
                if (EPI == 1) { v0 = rs * gelu_f(v0); v1 = rs * gelu_f(v1); }
                if (EPI == 3) { v0 *= rs; v1 *= rs; }
                if (sizeof(OutT) == 2) {
                    __half2 hv = __floats2half2_rn(v0, v1);
                    *(__half2*)((__half*)Crow + col) = hv;
                } else {
                    *(float2*)((float*)Crow + col) = make_float2(v0, v1);
                }
            }
        }
    }
}

// ---------------- launch -----------------------------------------------------
extern "C" void kernel_launch(void* const* d_in, const int* in_sizes, int n_in,
                              void* d_out, int out_size)
{
    const float* x      = (const float*)d_in[0];
    const float* c1a    = (const float*)d_in[1];
    const float* c1b    = (const float*)d_in[2];
    const float* c2a    = (const float*)d_in[3];
    const float* c2b    = (const float*)d_in[4];
    const float* hd_in  = (const float*)d_in[5];
    const float* hd_out = (const float*)d_in[6];
    const float* pb     = (const float*)d_in[7];
    const float* pw     = (const float*)d_in[8];
    float* out = (float*)d_out;

    __half *W1h, *W2n, *Wf, *hdinTh, *hdoutTh, *xh, *hall, *colh;
    cudaGetSymbolAddress((void**)&W1h,     g_W1h);
    cudaGetSymbolAddress((void**)&W2n,     g_W2n);
    cudaGetSymbolAddress((void**)&Wf,      g_Wf);
    cudaGetSymbolAddress((void**)&hdinTh,  g_hdinTh);
    cudaGetSymbolAddress((void**)&hdoutTh, g_hdoutTh);
    cudaGetSymbolAddress((void**)&xh,      g_xh);
    cudaGetSymbolAddress((void**)&hall,    g_hall);
    cudaGetSymbolAddress((void**)&colh,    g_colh);

    static bool attr_set = false;
    if (!attr_set) {
        cudaFuncSetAttribute(tgemm<0, float>,  cudaFuncAttributeMaxDynamicSharedMemorySize, GEMM_SMEM);
        cudaFuncSetAttribute(tgemm<0, __half>, cudaFuncAttributeMaxDynamicSharedMemorySize, GEMM_SMEM);
        cudaFuncSetAttribute(tgemm<1, __half>, cudaFuncAttributeMaxDynamicSharedMemorySize, GEMM_SMEM);
        cudaFuncSetAttribute(tgemm<3, __half>, cudaFuncAttributeMaxDynamicSharedMemorySize, GEMM_SMEM);
        attr_set = true;
    }

    // 1. build fp16 operands + routing matrix
    build_w1h<<<(KPATH * DFF * DMODEL + 255) / 256, 256>>>(c1a, c1b);
    build_w2n<<<(KPATH * DFF * DMODEL + 255) / 256, 256>>>(c2a, c2b);
    conv_x<<<(BATCH * DMODEL + 255) / 256, 256>>>(x);
    transpose_hdin<<<(DMODEL * HD + 255) / 256, 256>>>(hd_in);
    transpose_hdout<<<(HD * DMODEL + 255) / 256, 256>>>(hd_out);
    build_S<<<(DMODEL * 32 + 255) / 256, 256>>>(hd_in, pb);

    // 2. routing probs directly from x (scores = x @ S)
    routing_kernel<<<(BATCH * 32 + 255) / 256, 256>>>(x);

    // 3. folded tail weights into concat layout:
    //    Wf[hd][k*4096+j] = (hd_inT @ W2_k^T)[hd][j] * pw_k[hd]
    tgemm<3, __half><<<dim3(DFF / BN, HD / BM, KPATH), NT, GEMM_SMEM>>>(
        hdinTh, W2n, Wf, HD, DFF, DMODEL, KCAT, pw,
        0, (size_t)DFF * DMODEL, (size_t)DFF);

    // 4. h'[b][k*4096+j] = probs[b,k] * gelu((x @ W1_k)[b][j])
    tgemm<1, __half><<<dim3(DFF / BN, BATCH / BM, KPATH), NT, GEMM_SMEM>>>(
        xh, W1h, hall, BATCH, DFF, DMODEL, KCAT, nullptr,
        0, (size_t)DFF * DMODEL, (size_t)DFF);

    // 5. col = h'_cat @ Wf_cat^T  (single K=16384 GEMM, fp32 accum -> half)
    tgemm<0, __half><<<dim3(HD / BN, BATCH / BM, 1), NT, GEMM_SMEM>>>(
        hall, Wf, colh, BATCH, HD, KCAT, HD, nullptr, 0, 0, 0);

    // 6. out = col @ hd_out (fp32)
    tgemm<0, float><<<dim3(DMODEL / BN, BATCH / BM, 1), NT, GEMM_SMEM>>>(
        colh, hdoutTh, out, BATCH, DMODEL, HD, DMODEL, nullptr, 0, 0, 0);
}

// round 12
// speedup vs baseline: 1.0280x; 1.0280x over previous
#include <cuda_runtime.h>
#include <cuda_fp16.h>
#include <math.h>
#include <stdint.h>

// Problem constants
#define BATCH   8192
#define DMODEL  1024
#define DFF     4096
#define KPATH   4
#define RANK    16
#define HD      512

// ---------------- scratch (device globals; no allocation allowed) ----------
__device__ __half g_W1h[KPATH * DFF * DMODEL];   // [k][4096][1024] (N,K) 32MB
__device__ __half g_W2n[KPATH * DFF * DMODEL];   // [k][4096][1024] natural 32MB
__device__ __half g_Wfh[KPATH * HD * DFF];       // [k][512][4096] 16MB
__device__ __half g_hdinTh[HD * DMODEL];
__device__ __half g_hdoutTh[DMODEL * HD];
__device__ __half g_xh[BATCH * DMODEL];          // 16MB
__device__ __half g_h4[(size_t)KPATH * BATCH * DFF];   // 256MB
__device__ float  g_col4[(size_t)KPATH * BATCH * HD];  // 64MB
__device__ __half g_colh[BATCH * HD];            // 8MB
__device__ float  g_S[DMODEL * KPATH];           // routing mat [1024][4]
__device__ float  g_probs[BATCH * KPATH];

// ---------------- builders / converters -------------------------------------
__global__ void build_w1h(const float* __restrict__ c1a, const float* __restrict__ c1b) {
    int idx = blockIdx.x * blockDim.x + threadIdx.x;
    if (idx >= KPATH * DFF * DMODEL) return;
    int d  = idx & (DMODEL - 1);
    int t  = idx >> 10;
    int nn = t & (DFF - 1);
    int k  = t >> 12;
    int m = d >> 5, p = d & 31;
    int n = nn >> 6, o = nn & 63;
    const float* a = c1a + (((k * 32 + m) * 64 + n) * 16);
    const float* b = c1b + ((size_t)(k * 16) * 32 + p) * 64 + o;
    float s = 0.f;
#pragma unroll
    for (int r = 0; r < RANK; r++) s += a[r] * b[(size_t)r * 32 * 64];
    g_W1h[idx] = __float2half(s);
}

__global__ void build_w2n(const float* __restrict__ c2a, const float* __restrict__ c2b) {
    int idx = blockIdx.x * blockDim.x + threadIdx.x;
    if (idx >= KPATH * DFF * DMODEL) return;
    int dm = idx & (DMODEL - 1);
    int t  = idx >> 10;
    int ff = t & (DFF - 1);
    int k  = t >> 12;
    int n = dm >> 5, o = dm & 31;
    int m = ff >> 6, p = ff & 63;
    const float* a = c2a + (((k * 64 + m) * 32 + n) * 16);
    const float* b = c2b + ((size_t)(k * 16) * 64 + p) * 32 + o;
    float s = 0.f;
#pragma unroll
    for (int r = 0; r < RANK; r++) s += a[r] * b[(size_t)r * 64 * 32];
    g_W2n[idx] = __float2half(s);
}

// merged: x->fp16, hd_in transpose->fp16, hd_out transpose->fp16
#define PREP_N1 (BATCH * DMODEL)
#define PREP_N2 (DMODEL * HD)
#define PREP_TOT (PREP_N1 + 2 * PREP_N2)
__global__ void prep(const float* __restrict__ x,
                     const float* __restrict__ hd_in,
                     const float* __restrict__ hd_out) {
    for (int i = blockIdx.x * blockDim.x + threadIdx.x; i < PREP_TOT;
         i += gridDim.x * blockDim.x) {
        if (i < PREP_N1) {
            g_xh[i] = __float2half(x[i]);
        } else if (i < PREP_N1 + PREP_N2) {
            int j = i - PREP_N1;
            int d = j / HD, h2 = j % HD;
            g_hdinTh[(size_t)h2 * DMODEL + d] = __float2half(hd_in[j]);
        } else {
            int j = i - PREP_N1 - PREP_N2;
            int h2 = j / DMODEL, d = j % DMODEL;
            g_hdoutTh[(size_t)d * HD + h2] = __float2half(hd_out[j]);
        }
    }
}

// S[d][k] = sum_h hd_in[d,h] * pb[k,h]
__global__ void build_S(const float* __restrict__ hd_in, const float* __restrict__ pb) {
    int gid  = blockIdx.x * blockDim.x + threadIdx.x;
    int d    = gid >> 5;
    int lane = gid & 31;
    if (d >= DMODEL) return;
    const float* hr = hd_in + (size_t)d * HD;
    float s0 = 0.f, s1 = 0.f, s2 = 0.f, s3 = 0.f;
    for (int h = lane; h < HD; h += 32) {
        float v = hr[h];
        s0 += v * pb[0 * HD + h];
        s1 += v * pb[1 * HD + h];
        s2 += v * pb[2 * HD + h];
        s3 += v * pb[3 * HD + h];
    }
#pragma unroll
    for (int off = 16; off; off >>= 1) {
        s0 += __shfl_xor_sync(0xffffffffu, s0, off);
        s1 += __shfl_xor_sync(0xffffffffu, s1, off);
        s2 += __shfl_xor_sync(0xffffffffu, s2, off);
        s3 += __shfl_xor_sync(0xffffffffu, s3, off);
    }
    if (lane == 0) {
        g_S[d * 4 + 0] = s0; g_S[d * 4 + 1] = s1;
        g_S[d * 4 + 2] = s2; g_S[d * 4 + 3] = s3;
    }
}

// probs[b,:] = softmax(x[b,:] @ S)
__global__ void routing_kernel(const float* __restrict__ x) {
    int gid  = blockIdx.x * blockDim.x + threadIdx.x;
    int b    = gid >> 5;
    int lane = gid & 31;
    if (b >= BATCH) return;
    const float* xr = x + (size_t)b * DMODEL;
    float s0 = 0.f, s1 = 0.f, s2 = 0.f, s3 = 0.f;
    for (int d = lane; d < DMODEL; d += 32) {
        float v = xr[d];
        float4 S4 = *(const float4*)&g_S[d * 4];
        s0 += v * S4.x; s1 += v * S4.y; s2 += v * S4.z; s3 += v * S4.w;
    }
#pragma unroll
    for (int off = 16; off; off >>= 1) {
        s0 += __shfl_xor_sync(0xffffffffu, s0, off);
        s1 += __shfl_xor_sync(0xffffffffu, s1, off);
        s2 += __shfl_xor_sync(0xffffffffu, s2, off);
        s3 += __shfl_xor_sync(0xffffffffu, s3, off);
    }
    if (lane == 0) {
        float mx = fmaxf(fmaxf(s0, s1), fmaxf(s2, s3));
        float e0 = expf(s0 - mx), e1 = expf(s1 - mx);
        float e2 = expf(s2 - mx), e3 = expf(s3 - mx);
        float inv = 1.0f / (e0 + e1 + e2 + e3);
        g_probs[b * 4 + 0] = e0 * inv;
        g_probs[b * 4 + 1] = e1 * inv;
        g_probs[b * 4 + 2] = e2 * inv;
        g_probs[b * 4 + 3] = e3 * inv;
    }
}

__global__ void reduce_col() {
    int i = blockIdx.x * blockDim.x + threadIdx.x;
    if (i >= BATCH * HD) return;
    const size_t SZ = (size_t)BATCH * HD;
    float s = g_col4[i] + g_col4[SZ + i] + g_col4[2 * SZ + i] + g_col4[3 * SZ + i];
    g_colh[i] = __float2half(s);
}

// ---------------- fp16 mma.sync m16n8k16 GEMM, z-batched -------------------
// CTA 128x128, BK=64, SW128, 3 stages. 128 threads = 4 warps (2x2), warp 64x64.
#define BM 128
#define BN 128
#define BK 64
#define STAGES 3
#define TILEB (BM * 128)
#define STAGEB (2 * TILEB)
#define GEMM_SMEM (STAGES * STAGEB)    // 98304
#define NT 128

__device__ __forceinline__ void cp16(uint32_t dst, const void* src) {
    asm volatile("cp.async.cg.shared.global [%0], [%1], 16;"
                 :: "r"(dst), "l"(src) : "memory");
}
__device__ __forceinline__ void cp_commit() {
    asm volatile("cp.async.commit_group;" ::: "memory");
}
template <int N>
__device__ __forceinline__ void cp_wait() {
    asm volatile("cp.async.wait_group %0;" :: "n"(N) : "memory");
}
__device__ __forceinline__ void ldsm4(uint32_t* r, uint32_t addr) {
    asm volatile("ldmatrix.sync.aligned.m8n8.x4.shared.b16 {%0,%1,%2,%3}, [%4];"
                 : "=r"(r[0]), "=r"(r[1]), "=r"(r[2]), "=r"(r[3]) : "r"(addr));
}
__device__ __forceinline__ void mma16816(float* c, const uint32_t* a, const uint32_t* b) {
    asm volatile(
        "mma.sync.aligned.m16n8k16.row.col.f32.f16.f16.f32 "
        "{%0,%1,%2,%3}, {%4,%5,%6,%7}, {%8,%9}, {%0,%1,%2,%3};"
        : "+f"(c[0]), "+f"(c[1]), "+f"(c[2]), "+f"(c[3])
        : "r"(a[0]), "r"(a[1]), "r"(a[2]), "r"(a[3]), "r"(b[0]), "r"(b[1]));
}

__device__ __forceinline__ float gelu_f(float v) {
    float u = 1.5957691216057308f * (v + 0.044715f * v * v * v);
    return v * (1.0f / (1.0f + __expf(-u)));
}

// EPI: 0 = plain, 1 = gelu->half, 2 = probs-scale -> fp32 partial,
//      3 = pw-row-scale -> half (Wf precompute)
template <int EPI, typename OutT>
__global__ __launch_bounds__(NT, 2)
void tgemm(const __half* __restrict__ A, const __half* __restrict__ Bt,
           OutT* __restrict__ C, int M, int N, int Kd,
           const float* __restrict__ pw,
           size_t saz, size_t sbz, size_t scz)
{
    extern __shared__ char smem[];
    uint32_t sbase = (uint32_t)__cvta_generic_to_shared(smem);

    int tid  = threadIdx.x;
    int wid  = tid >> 5;
    int lane = tid & 31;
    int g    = lane >> 2;
    int tig  = lane & 3;
    int wm   = wid & 1;        // 2 warps in M, 64 rows each
    int wn   = wid >> 1;       // 2 warps in N, 64 cols each
    int kz   = blockIdx.z;

    const __half* Ab = A  + (size_t)kz * saz + (size_t)blockIdx.y * BM * Kd;
    const __half* Bb = Bt + (size_t)kz * sbz + (size_t)blockIdx.x * BN * Kd;
    OutT* Cb = C + (size_t)kz * scz;
    int KT = Kd / BK;

    float acc[4][8][4];
#pragma unroll
    for (int i = 0; i < 4; i++)
#pragma unroll
        for (int j = 0; j < 8; j++)
#pragma unroll
            for (int q = 0; q < 4; q++) acc[i][j][q] = 0.f;

    uint32_t xm      = (uint32_t)(lane & 7) << 4;
    uint32_t a_row   = (uint32_t)(wm * 64 + (lane & 15)) * 128;
    uint32_t a_klane = (uint32_t)((lane >> 1) & 8) * 2;
    int nlo          = (lane & 7) | ((lane & 16) >> 1);
    uint32_t b_klane = (uint32_t)(lane & 8) * 2;

    auto load_stage = [&](int stage, int kt) {
        uint32_t abase = sbase + stage * STAGEB;
        uint32_t bbase = abase + TILEB;
        const __half* As = Ab + (size_t)kt * BK;
        const __half* Bs = Bb + (size_t)kt * BK;
#pragma unroll
        for (int i = 0; i < 8; i++) {
            int c   = tid + NT * i;       // 0..1023
            int row = c >> 3;
            int ch  = c & 7;
            uint32_t off = (uint32_t)row * 128 + (uint32_t)ch * 16;
            uint32_t sw  = off ^ ((off >> 3) & 0x70);
            cp16(abase + sw, As + (size_t)row * Kd + ch * 8);
            cp16(bbase + sw, Bs + (size_t)row * Kd + ch * 8);
        }
    };

#pragma unroll
    for (int s = 0; s < STAGES - 1; s++) {
        if (s < KT) load_stage(s, s);
        cp_commit();
    }

    for (int kt = 0; kt < KT; kt++) {
        cp_wait<STAGES - 2>();
        __syncthreads();

        int nxt = kt + STAGES - 1;
        if (nxt < KT) load_stage(nxt % STAGES, nxt);
        cp_commit();

        uint32_t abase = sbase + (kt % STAGES) * STAGEB;
        uint32_t bbase = abase + TILEB;

#pragma unroll
        for (int ks = 0; ks < 4; ks++) {
            uint32_t kb = (uint32_t)ks * 32;
            uint32_t af[4][4];
#pragma unroll
            for (int mf = 0; mf < 4; mf++)
                ldsm4(af[mf], abase + a_row + (uint32_t)mf * 16 * 128 +
                                ((kb + a_klane) ^ xm));
            uint32_t bf[4][4];
#pragma unroll
            for (int ng = 0; ng < 4; ng++)
                ldsm4(bf[ng], bbase + (uint32_t)(wn * 64 + ng * 16 + nlo) * 128 +
                                ((kb + b_klane) ^ xm));
#pragma unroll
            for (int mf = 0; mf < 4; mf++)
#pragma unroll
                for (int ng = 0; ng < 4; ng++) {
                    mma16816(acc[mf][2 * ng + 0], af[mf], &bf[ng][0]);
                    mma16816(acc[mf][2 * ng + 1], af[mf], &bf[ng][2]);
                }
        }
        __syncthreads();
    }

    // ---- epilogue ----
#pragma unroll
    for (int mf = 0; mf < 4; mf++) {
        int row0 = blockIdx.y * BM + wm * 64 + mf * 16 + g;
#pragma unroll
        for (int half = 0; half < 2; half++) {
            int row = row0 + half * 8;
            float rs = 1.f;
            if (EPI == 2) rs = g_probs[row * KPATH + kz];
            if (EPI == 3) rs = pw[kz * HD + row];
            OutT* Crow = Cb + (size_t)row * N;
#pragma unroll
            for (int nf = 0; nf < 8; nf++) {
                int col = blockIdx.x * BN + wn * 64 + (nf >> 1) * 16 + (nf & 1) * 8 + 2 * tig;
                float v0 = acc[mf][nf][half * 2 + 0];
                float v1 = acc[mf][nf][half * 2 + 1];
                if (EPI == 1) { v0 = gelu_f(v0); v1 = gelu_f(v1); }
                if (EPI == 2 || EPI == 3) { v0 *= rs; v1 *= rs; }
                if (sizeof(OutT) == 2) {
                    __half2 hv = __floats2half2_rn(v0, v1);
                    *(__half2*)((__half*)Crow + col) = hv;
                } else {
                    *(float2*)((float*)Crow + col) = make_float2(v0, v1);
                }
            }
        }
    }
}

// ---------------- launch -----------------------------------------------------
extern "C" void kernel_launch(void* const* d_in, const int* in_sizes, int n_in,
                              void* d_out, int out_size)
{
    const float* x      = (const float*)d_in[0];
    const float* c1a    = (const float*)d_in[1];
    const float* c1b    = (const float*)d_in[2];
    const float* c2a    = (const float*)d_in[3];
    const float* c2b    = (const float*)d_in[4];
    const float* hd_in  = (const float*)d_in[5];
    const float* hd_out = (const float*)d_in[6];
    const float* pb     = (const float*)d_in[7];
    const float* pw     = (const float*)d_in[8];
    float* out = (float*)d_out;

    __half *W1h, *W2n, *Wfh, *hdinTh, *hdoutTh, *xh, *h4, *colh;
    float *col4;
    cudaGetSymbolAddress((void**)&W1h,     g_W1h);
    cudaGetSymbolAddress((void**)&W2n,     g_W2n);
    cudaGetSymbolAddress((void**)&Wfh,     g_Wfh);
    cudaGetSymbolAddress((void**)&hdinTh,  g_hdinTh);
    cudaGetSymbolAddress((void**)&hdoutTh, g_hdoutTh);
    cudaGetSymbolAddress((void**)&xh,      g_xh);
    cudaGetSymbolAddress((void**)&h4,      g_h4);
    cudaGetSymbolAddress((void**)&colh,    g_colh);
    cudaGetSymbolAddress((void**)&col4,    g_col4);

    static bool attr_set = false;
    if (!attr_set) {
        cudaFuncSetAttribute(tgemm<0, float>,  cudaFuncAttributeMaxDynamicSharedMemorySize, GEMM_SMEM);
        cudaFuncSetAttribute(tgemm<1, __half>, cudaFuncAttributeMaxDynamicSharedMemorySize, GEMM_SMEM);
        cudaFuncSetAttribute(tgemm<2, float>,  cudaFuncAttributeMaxDynamicSharedMemorySize, GEMM_SMEM);
        cudaFuncSetAttribute(tgemm<3, __half>, cudaFuncAttributeMaxDynamicSharedMemorySize, GEMM_SMEM);
        attr_set = true;
    }

    // launches 0-4 (so ncu -s 5 captures GEMM1 below)
    build_w1h<<<(KPATH * DFF * DMODEL + 255) / 256, 256>>>(c1a, c1b);          // 0
    build_w2n<<<(KPATH * DFF * DMODEL + 255) / 256, 256>>>(c2a, c2b);          // 1
    prep<<<2048, 256>>>(x, hd_in, hd_out);                                     // 2
    build_S<<<(DMODEL * 32 + 255) / 256, 256>>>(hd_in, pb);                    // 3
    routing_kernel<<<(BATCH * 32 + 255) / 256, 256>>>(x);                      // 4

    // 5: h_k = gelu(x @ W1_k), all paths (PROFILED LAUNCH)
    tgemm<1, __half><<<dim3(DFF / BN, BATCH / BM, KPATH), NT, GEMM_SMEM>>>(
        xh, W1h, h4, BATCH, DFF, DMODEL, nullptr,
        0, (size_t)DFF * DMODEL, (size_t)BATCH * DFF);

    // 6: folded tail weights WfT_k[512,4096] = (hd_inT @ W2_k^T) * pw_k(row)
    tgemm<3, __half><<<dim3(DFF / BN, HD / BM, KPATH), NT, GEMM_SMEM>>>(
        hdinTh, W2n, Wfh, HD, DFF, DMODEL, pw,
        0, (size_t)DFF * DMODEL, (size_t)HD * DFF);

    // 7: col4_k = probs[:,k] * (h_k @ Wf_k), z-batched (1024 CTAs, balanced)
    tgemm<2, float><<<dim3(HD / BN, BATCH / BM, KPATH), NT, GEMM_SMEM>>>(
        h4, Wfh, col4, BATCH, HD, DFF, nullptr,
        (size_t)BATCH * DFF, (size_t)HD * DFF, (size_t)BATCH * HD);

    // 8: reduce partials -> colh (fp16)
    reduce_col<<<(BATCH * HD + 255) / 256, 256>>>();

    // 9: out = col @ hd_out (fp32)
    tgemm<0, float><<<dim3(DMODEL / BN, BATCH / BM, 1), NT, GEMM_SMEM>>>(
        colh, hdoutTh, out, BATCH, DMODEL, HD, nullptr, 0, 0, 0);
}

// round 13
// speedup vs baseline: 1.0306x; 1.0025x over previous
#include <cuda_runtime.h>
#include <cuda_fp16.h>
#include <math.h>
#include <stdint.h>

// Problem constants
#define BATCH   8192
#define DMODEL  1024
#define DFF     4096
#define KPATH   4
#define RANK    16
#define HD      512

// ---------------- scratch (device globals; no allocation allowed) ----------
__device__ __half g_W1h[KPATH * DFF * DMODEL];   // [k][4096][1024] (N,K) 32MB
__device__ __half g_W2n[KPATH * DFF * DMODEL];   // [k][4096][1024] natural 32MB
__device__ __half g_Wfh[KPATH * HD * DFF];       // [k][512][4096] 16MB
__device__ __half g_hdinTh[HD * DMODEL];
__device__ __half g_hdoutTh[DMODEL * HD];
__device__ __half g_xh[BATCH * DMODEL];          // 16MB
__device__ __half g_h4[(size_t)KPATH * BATCH * DFF];   // 256MB
__device__ float  g_col4[(size_t)KPATH * BATCH * HD];  // 64MB
__device__ __half g_colh[BATCH * HD];            // 8MB
__device__ float  g_S[DMODEL * KPATH];           // routing mat [1024][4]
__device__ float  g_probs[BATCH * KPATH];

// ---------------- builders / converters -------------------------------------
__global__ void build_w1h(const float* __restrict__ c1a, const float* __restrict__ c1b) {
    int idx = blockIdx.x * blockDim.x + threadIdx.x;
    if (idx >= KPATH * DFF * DMODEL) return;
    int d  = idx & (DMODEL - 1);
    int t  = idx >> 10;
    int nn = t & (DFF - 1);
    int k  = t >> 12;
    int m = d >> 5, p = d & 31;
    int n = nn >> 6, o = nn & 63;
    const float* a = c1a + (((k * 32 + m) * 64 + n) * 16);
    const float* b = c1b + ((size_t)(k * 16) * 32 + p) * 64 + o;
    float s = 0.f;
#pragma unroll
    for (int r = 0; r < RANK; r++) s += a[r] * b[(size_t)r * 32 * 64];
    g_W1h[idx] = __float2half(s);
}

__global__ void build_w2n(const float* __restrict__ c2a, const float* __restrict__ c2b) {
    int idx = blockIdx.x * blockDim.x + threadIdx.x;
    if (idx >= KPATH * DFF * DMODEL) return;
    int dm = idx & (DMODEL - 1);
    int t  = idx >> 10;
    int ff = t & (DFF - 1);
    int k  = t >> 12;
    int n = dm >> 5, o = dm & 31;
    int m = ff >> 6, p = ff & 63;
    const float* a = c2a + (((k * 64 + m) * 32 + n) * 16);
    const float* b = c2b + ((size_t)(k * 16) * 64 + p) * 32 + o;
    float s = 0.f;
#pragma unroll
    for (int r = 0; r < RANK; r++) s += a[r] * b[(size_t)r * 64 * 32];
    g_W2n[idx] = __float2half(s);
}

// merged: x->fp16, hd_in transpose->fp16, hd_out transpose->fp16
#define PREP_N1 (BATCH * DMODEL)
#define PREP_N2 (DMODEL * HD)
#define PREP_TOT (PREP_N1 + 2 * PREP_N2)
__global__ void prep(const float* __restrict__ x,
                     const float* __restrict__ hd_in,
                     const float* __restrict__ hd_out) {
    for (int i = blockIdx.x * blockDim.x + threadIdx.x; i < PREP_TOT;
         i += gridDim.x * blockDim.x) {
        if (i < PREP_N1) {
            g_xh[i] = __float2half(x[i]);
        } else if (i < PREP_N1 + PREP_N2) {
            int j = i - PREP_N1;
            int d = j / HD, h2 = j % HD;
            g_hdinTh[(size_t)h2 * DMODEL + d] = __float2half(hd_in[j]);
        } else {
            int j = i - PREP_N1 - PREP_N2;
            int h2 = j / DMODEL, d = j % DMODEL;
            g_hdoutTh[(size_t)d * HD + h2] = __float2half(hd_out[j]);
        }
    }
}

// S[d][k] = sum_h hd_in[d,h] * pb[k,h]
__global__ void build_S(const float* __restrict__ hd_in, const float* __restrict__ pb) {
    int gid  = blockIdx.x * blockDim.x + threadIdx.x;
    int d    = gid >> 5;
    int lane = gid & 31;
    if (d >= DMODEL) return;
    const float* hr = hd_in + (size_t)d * HD;
    float s0 = 0.f, s1 = 0.f, s2 = 0.f, s3 = 0.f;
    for (int h = lane; h < HD; h += 32) {
        float v = hr[h];
        s0 += v * pb[0 * HD + h];
        s1 += v * pb[1 * HD + h];
        s2 += v * pb[2 * HD + h];
        s3 += v * pb[3 * HD + h];
    }
#pragma unroll
    for (int off = 16; off; off >>= 1) {
        s0 += __shfl_xor_sync(0xffffffffu, s0, off);
        s1 += __shfl_xor_sync(0xffffffffu, s1, off);
        s2 += __shfl_xor_sync(0xffffffffu, s2, off);
        s3 += __shfl_xor_sync(0xffffffffu, s3, off);
    }
    if (lane == 0) {
        g_S[d * 4 + 0] = s0; g_S[d * 4 + 1] = s1;
        g_S[d * 4 + 2] = s2; g_S[d * 4 + 3] = s3;
    }
}

// probs[b,:] = softmax(x[b,:] @ S)
__global__ void routing_kernel(const float* __restrict__ x) {
    int gid  = blockIdx.x * blockDim.x + threadIdx.x;
    int b    = gid >> 5;
    int lane = gid & 31;
    if (b >= BATCH) return;
    const float* xr = x + (size_t)b * DMODEL;
    float s0 = 0.f, s1 = 0.f, s2 = 0.f, s3 = 0.f;
    for (int d = lane; d < DMODEL; d += 32) {
        float v = xr[d];
        float4 S4 = *(const float4*)&g_S[d * 4];
        s0 += v * S4.x; s1 += v * S4.y; s2 += v * S4.z; s3 += v * S4.w;
    }
#pragma unroll
    for (int off = 16; off; off >>= 1) {
        s0 += __shfl_xor_sync(0xffffffffu, s0, off);
        s1 += __shfl_xor_sync(0xffffffffu, s1, off);
        s2 += __shfl_xor_sync(0xffffffffu, s2, off);
        s3 += __shfl_xor_sync(0xffffffffu, s3, off);
    }
    if (lane == 0) {
        float mx = fmaxf(fmaxf(s0, s1), fmaxf(s2, s3));
        float e0 = expf(s0 - mx), e1 = expf(s1 - mx);
        float e2 = expf(s2 - mx), e3 = expf(s3 - mx);
        float inv = 1.0f / (e0 + e1 + e2 + e3);
        g_probs[b * 4 + 0] = e0 * inv;
        g_probs[b * 4 + 1] = e1 * inv;
        g_probs[b * 4 + 2] = e2 * inv;
        g_probs[b * 4 + 3] = e3 * inv;
    }
}

__global__ void reduce_col() {
    int i = blockIdx.x * blockDim.x + threadIdx.x;
    if (i >= BATCH * HD) return;
    const size_t SZ = (size_t)BATCH * HD;
    float s = g_col4[i] + g_col4[SZ + i] + g_col4[2 * SZ + i] + g_col4[3 * SZ + i];
    g_colh[i] = __float2half(s);
}

// ---------------- fp16 mma.sync m16n8k16 GEMM, z-batched -------------------
// CTA 128x128, BK=64, SW128, 3 stages. 128 threads = 4 warps (2x2), warp 64x64.
// ONE barrier per k-iteration: the post-cp_wait barrier already orders
// "all warps done computing stage s" before "any warp overwrites stage s".
#define BM 128
#define BN 128
#define BK 64
#define STAGES 3
#define TILEB (BM * 128)
#define STAGEB (2 * TILEB)
#define GEMM_SMEM (STAGES * STAGEB)    // 98304
#define NT 128

__device__ __forceinline__ void cp16(uint32_t dst, const void* src) {
    asm volatile("cp.async.cg.shared.global [%0], [%1], 16;"
                 :: "r"(dst), "l"(src) : "memory");
}
__device__ __forceinline__ void cp_commit() {
    asm volatile("cp.async.commit_group;" ::: "memory");
}
template <int N>
__device__ __forceinline__ void cp_wait() {
    asm volatile("cp.async.wait_group %0;" :: "n"(N) : "memory");
}
__device__ __forceinline__ void ldsm4(uint32_t* r, uint32_t addr) {
    asm volatile("ldmatrix.sync.aligned.m8n8.x4.shared.b16 {%0,%1,%2,%3}, [%4];"
                 : "=r"(r[0]), "=r"(r[1]), "=r"(r[2]), "=r"(r[3]) : "r"(addr));
}
__device__ __forceinline__ void mma16816(float* c, const uint32_t* a, const uint32_t* b) {
    asm volatile(
        "mma.sync.aligned.m16n8k16.row.col.f32.f16.f16.f32 "
        "{%0,%1,%2,%3}, {%4,%5,%6,%7}, {%8,%9}, {%0,%1,%2,%3};"
        : "+f"(c[0]), "+f"(c[1]), "+f"(c[2]), "+f"(c[3])
        : "r"(a[0]), "r"(a[1]), "r"(a[2]), "r"(a[3]), "r"(b[0]), "r"(b[1]));
}

__device__ __forceinline__ float gelu_f(float v) {
    float u = 1.5957691216057308f * (v + 0.044715f * v * v * v);
    return v * (1.0f / (1.0f + __expf(-u)));
}

// EPI: 0 = plain, 1 = gelu->half, 2 = probs-scale -> fp32 partial,
//      3 = pw-row-scale -> half (Wf precompute)
template <int EPI, typename OutT>
__global__ __launch_bounds__(NT, 2)
void tgemm(const __half* __restrict__ A, const __half* __restrict__ Bt,
           OutT* __restrict__ C, int M, int N, int Kd,
           const float* __restrict__ pw,
           size_t saz, size_t sbz, size_t scz)
{
    extern __shared__ char smem[];
    uint32_t sbase = (uint32_t)__cvta_generic_to_shared(smem);

    int tid  = threadIdx.x;
    int wid  = tid >> 5;
    int lane = tid & 31;
    int g    = lane >> 2;
    int tig  = lane & 3;
    int wm   = wid & 1;        // 2 warps in M, 64 rows each
    int wn   = wid >> 1;       // 2 warps in N, 64 cols each
    int kz   = blockIdx.z;

    const __half* Ab = A  + (size_t)kz * saz + (size_t)blockIdx.y * BM * Kd;
    const __half* Bb = Bt + (size_t)kz * sbz + (size_t)blockIdx.x * BN * Kd;
    OutT* Cb = C + (size_t)kz * scz;
    int KT = Kd / BK;

    float acc[4][8][4];
#pragma unroll
    for (int i = 0; i < 4; i++)
#pragma unroll
        for (int j = 0; j < 8; j++)
#pragma unroll
            for (int q = 0; q < 4; q++) acc[i][j][q] = 0.f;

    uint32_t xm      = (uint32_t)(lane & 7) << 4;
    uint32_t a_row   = (uint32_t)(wm * 64 + (lane & 15)) * 128;
    uint32_t a_klane = (uint32_t)((lane >> 1) & 8) * 2;
    int nlo          = (lane & 7) | ((lane & 16) >> 1);
    uint32_t b_klane = (uint32_t)(lane & 8) * 2;

    auto load_stage = [&](int stage, int kt) {
        uint32_t abase = sbase + stage * STAGEB;
        uint32_t bbase = abase + TILEB;
        const __half* As = Ab + (size_t)kt * BK;
        const __half* Bs = Bb + (size_t)kt * BK;
#pragma unroll
        for (int i = 0; i < 8; i++) {
            int c   = tid + NT * i;       // 0..1023
            int row = c >> 3;
            int ch  = c & 7;
            uint32_t off = (uint32_t)row * 128 + (uint32_t)ch * 16;
            uint32_t sw  = off ^ ((off >> 3) & 0x70);
            cp16(abase + sw, As + (size_t)row * Kd + ch * 8);
            cp16(bbase + sw, Bs + (size_t)row * Kd + ch * 8);
        }
    };

#pragma unroll
    for (int s = 0; s < STAGES - 1; s++) {
        if (s < KT) load_stage(s, s);
        cp_commit();
    }

    for (int kt = 0; kt < KT; kt++) {
        cp_wait<STAGES - 2>();
        __syncthreads();   // stage kt ready; all warps past compute of kt-1

        int nxt = kt + STAGES - 1;
        if (nxt < KT) load_stage(nxt % STAGES, nxt);
        cp_commit();

        uint32_t abase = sbase + (kt % STAGES) * STAGEB;
        uint32_t bbase = abase + TILEB;

#pragma unroll
        for (int ks = 0; ks < 4; ks++) {
            uint32_t kb = (uint32_t)ks * 32;
            uint32_t af[4][4];
#pragma unroll
            for (int mf = 0; mf < 4; mf++)
                ldsm4(af[mf], abase + a_row + (uint32_t)mf * 16 * 128 +
                                ((kb + a_klane) ^ xm));
            uint32_t bf[4][4];
#pragma unroll
            for (int ng = 0; ng < 4; ng++)
                ldsm4(bf[ng], bbase + (uint32_t)(wn * 64 + ng * 16 + nlo) * 128 +
                                ((kb + b_klane) ^ xm));
#pragma unroll
            for (int mf = 0; mf < 4; mf++)
#pragma unroll
                for (int ng = 0; ng < 4; ng++) {
                    mma16816(acc[mf][2 * ng + 0], af[mf], &bf[ng][0]);
                    mma16816(acc[mf][2 * ng + 1], af[mf], &bf[ng][2]);
                }
        }
        // no trailing barrier: next iteration's leading barrier provides the
        // read-complete -> overwrite ordering for the 3-stage rotation.
    }

    // ---- epilogue ----
#pragma unroll
    for (int mf = 0; mf < 4; mf++) {
        int row0 = blockIdx.y * BM + wm * 64 + mf * 16 + g;
#pragma unroll
        for (int half = 0; half < 2; half++) {
            int row = row0 + half * 8;
            float rs = 1.f;
            if (EPI == 2) rs = g_probs[row * KPATH + kz];
            if (EPI == 3) rs = pw[kz * HD + row];
            OutT* Crow = Cb + (size_t)row * N;
#pragma unroll
            for (int nf = 0; nf < 8; nf++) {
                int col = blockIdx.x * BN + wn * 64 + (nf >> 1) * 16 + (nf & 1) * 8 + 2 * tig;
                float v0 = acc[mf][nf][half * 2 + 0];
                float v1 = acc[mf][nf][half * 2 + 1];
                if (EPI == 1) { v0 = gelu_f(v0); v1 = gelu_f(v1); }
                if (EPI == 2 || EPI == 3) { v0 *= rs; v1 *= rs; }
                if (sizeof(OutT) == 2) {
                    __half2 hv = __floats2half2_rn(v0, v1);
                    *(__half2*)((__half*)Crow + col) = hv;
                } else {
                    *(float2*)((float*)Crow + col) = make_float2(v0, v1);
                }
            }
        }
    }
}

// ---------------- launch -----------------------------------------------------
extern "C" void kernel_launch(void* const* d_in, const int* in_sizes, int n_in,
                              void* d_out, int out_size)
{
    const float* x      = (const float*)d_in[0];
    const float* c1a    = (const float*)d_in[1];
    const float* c1b    = (const float*)d_in[2];
    const float* c2a    = (const float*)d_in[3];
    const float* c2b    = (const float*)d_in[4];
    const float* hd_in  = (const float*)d_in[5];
    const float* hd_out = (const float*)d_in[6];
    const float* pb     = (const float*)d_in[7];
    const float* pw     = (const float*)d_in[8];
    float* out = (float*)d_out;

    __half *W1h, *W2n, *Wfh, *hdinTh, *hdoutTh, *xh, *h4, *colh;
    float *col4;
    cudaGetSymbolAddress((void**)&W1h,     g_W1h);
    cudaGetSymbolAddress((void**)&W2n,     g_W2n);
    cudaGetSymbolAddress((void**)&Wfh,     g_Wfh);
    cudaGetSymbolAddress((void**)&hdinTh,  g_hdinTh);
    cudaGetSymbolAddress((void**)&hdoutTh, g_hdoutTh);
    cudaGetSymbolAddress((void**)&xh,      g_xh);
    cudaGetSymbolAddress((void**)&h4,      g_h4);
    cudaGetSymbolAddress((void**)&colh,    g_colh);
    cudaGetSymbolAddress((void**)&col4,    g_col4);

    static bool attr_set = false;
    if (!attr_set) {
        cudaFuncSetAttribute(tgemm<0, float>,  cudaFuncAttributeMaxDynamicSharedMemorySize, GEMM_SMEM);
        cudaFuncSetAttribute(tgemm<1, __half>, cudaFuncAttributeMaxDynamicSharedMemorySize, GEMM_SMEM);
        cudaFuncSetAttribute(tgemm<2, float>,  cudaFuncAttributeMaxDynamicSharedMemorySize, GEMM_SMEM);
        cudaFuncSetAttribute(tgemm<3, __half>, cudaFuncAttributeMaxDynamicSharedMemorySize, GEMM_SMEM);
        attr_set = true;
    }

    build_w1h<<<(KPATH * DFF * DMODEL + 255) / 256, 256>>>(c1a, c1b);          // 0
    build_w2n<<<(KPATH * DFF * DMODEL + 255) / 256, 256>>>(c2a, c2b);          // 1
    prep<<<2048, 256>>>(x, hd_in, hd_out);                                     // 2
    build_S<<<(DMODEL * 32 + 255) / 256, 256>>>(hd_in, pb);                    // 3
    routing_kernel<<<(BATCH * 32 + 255) / 256, 256>>>(x);                      // 4

    // 5: h_k = gelu(x @ W1_k), all paths
    tgemm<1, __half><<<dim3(DFF / BN, BATCH / BM, KPATH), NT, GEMM_SMEM>>>(
        xh, W1h, h4, BATCH, DFF, DMODEL, nullptr,
        0, (size_t)DFF * DMODEL, (size_t)BATCH * DFF);

    // 6: folded tail weights WfT_k[512,4096] = (hd_inT @ W2_k^T) * pw_k(row)
    tgemm<3, __half><<<dim3(DFF / BN, HD / BM, KPATH), NT, GEMM_SMEM>>>(
        hdinTh, W2n, Wfh, HD, DFF, DMODEL, pw,
        0, (size_t)DFF * DMODEL, (size_t)HD * DFF);

    // 7: col4_k = probs[:,k] * (h_k @ Wf_k), z-batched (1024 CTAs, balanced)
    tgemm<2, float><<<dim3(HD / BN, BATCH / BM, KPATH), NT, GEMM_SMEM>>>(
        h4, Wfh, col4, BATCH, HD, DFF, nullptr,
        (size_t)BATCH * DFF, (size_t)HD * DFF, (size_t)BATCH * HD);

    // 8: reduce partials -> colh (fp16)
    reduce_col<<<(BATCH * HD + 255) / 256, 256>>>();

    // 9: out = col @ hd_out (fp32)
    tgemm<0, float><<<dim3(DMODEL / BN, BATCH / BM, 1), NT, GEMM_SMEM>>>(
        colh, hdoutTh, out, BATCH, DMODEL, HD, nullptr, 0, 0, 0);
}

// round 15
// speedup vs baseline: 1.0437x; 1.0127x over previous
#include <cuda_runtime.h>
#include <cuda_fp16.h>
#include <math.h>
#include <stdint.h>

// Problem constants
#define BATCH   8192
#define DMODEL  1024
#define DFF     4096
#define KPATH   4
#define RANK    16
#define HD      512

// ---------------- scratch (device globals; no allocation allowed) ----------
__device__ __half g_W1h[KPATH * DFF * DMODEL];   // [k][4096][1024] (N,K) 32MB
__device__ __half g_W2n[KPATH * DFF * DMODEL];   // [k][4096][1024] natural 32MB
__device__ __half g_Wfh[KPATH * HD * DFF];       // [k][512][4096] 16MB
__device__ __half g_hdinTh[HD * DMODEL];
__device__ __half g_hdoutTh[DMODEL * HD];
__device__ __half g_xh[BATCH * DMODEL];          // 16MB
__device__ __half g_h4[(size_t)KPATH * BATCH * DFF];   // 256MB
__device__ float  g_col4[(size_t)KPATH * BATCH * HD];  // 64MB
__device__ __half g_colh[BATCH * HD];            // 8MB
__device__ float  g_S[DMODEL * KPATH];           // routing mat [1024][4]
__device__ float  g_probs[BATCH * KPATH];

// ---------------- builders / converters -------------------------------------
__global__ void build_w1h(const float* __restrict__ c1a, const float* __restrict__ c1b) {
    int idx = blockIdx.x * blockDim.x + threadIdx.x;
    if (idx >= KPATH * DFF * DMODEL) return;
    int d  = idx & (DMODEL - 1);
    int t  = idx >> 10;
    int nn = t & (DFF - 1);
    int k  = t >> 12;
    int m = d >> 5, p = d & 31;
    int n = nn >> 6, o = nn & 63;
    const float* a = c1a + (((k * 32 + m) * 64 + n) * 16);
    const float* b = c1b + ((size_t)(k * 16) * 32 + p) * 64 + o;
    float s = 0.f;
#pragma unroll
    for (int r = 0; r < RANK; r++) s += a[r] * b[(size_t)r * 32 * 64];
    g_W1h[idx] = __float2half(s);
}

__global__ void build_w2n(const float* __restrict__ c2a, const float* __restrict__ c2b) {
    int idx = blockIdx.x * blockDim.x + threadIdx.x;
    if (idx >= KPATH * DFF * DMODEL) return;
    int dm = idx & (DMODEL - 1);
    int t  = idx >> 10;
    int ff = t & (DFF - 1);
    int k  = t >> 12;
    int n = dm >> 5, o = dm & 31;
    int m = ff >> 6, p = ff & 63;
    const float* a = c2a + (((k * 64 + m) * 32 + n) * 16);
    const float* b = c2b + ((size_t)(k * 16) * 64 + p) * 32 + o;
    float s = 0.f;
#pragma unroll
    for (int r = 0; r < RANK; r++) s += a[r] * b[(size_t)r * 64 * 32];
    g_W2n[idx] = __float2half(s);
}

// merged: x->fp16, hd_in transpose->fp16, hd_out transpose->fp16
#define PREP_N1 (BATCH * DMODEL)
#define PREP_N2 (DMODEL * HD)
#define PREP_TOT (PREP_N1 + 2 * PREP_N2)
__global__ void prep(const float* __restrict__ x,
                     const float* __restrict__ hd_in,
                     const float* __restrict__ hd_out) {
    for (int i = blockIdx.x * blockDim.x + threadIdx.x; i < PREP_TOT;
         i += gridDim.x * blockDim.x) {
        if (i < PREP_N1) {
            g_xh[i] = __float2half(x[i]);
        } else if (i < PREP_N1 + PREP_N2) {
            int j = i - PREP_N1;
            int d = j / HD, h2 = j % HD;
            g_hdinTh[(size_t)h2 * DMODEL + d] = __float2half(hd_in[j]);
        } else {
            int j = i - PREP_N1 - PREP_N2;
            int h2 = j / DMODEL, d = j % DMODEL;
            g_hdoutTh[(size_t)d * HD + h2] = __float2half(hd_out[j]);
        }
    }
}

// S[d][k] = sum_h hd_in[d,h] * pb[k,h]
__global__ void build_S(const float* __restrict__ hd_in, const float* __restrict__ pb) {
    int gid  = blockIdx.x * blockDim.x + threadIdx.x;
    int d    = gid >> 5;
    int lane = gid & 31;
    if (d >= DMODEL) return;
    const float* hr = hd_in + (size_t)d * HD;
    float s0 = 0.f, s1 = 0.f, s2 = 0.f, s3 = 0.f;
    for (int h = lane; h < HD; h += 32) {
        float v = hr[h];
        s0 += v * pb[0 * HD + h];
        s1 += v * pb[1 * HD + h];
        s2 += v * pb[2 * HD + h];
        s3 += v * pb[3 * HD + h];
    }
#pragma unroll
    for (int off = 16; off; off >>= 1) {
        s0 += __shfl_xor_sync(0xffffffffu, s0, off);
        s1 += __shfl_xor_sync(0xffffffffu, s1, off);
        s2 += __shfl_xor_sync(0xffffffffu, s2, off);
        s3 += __shfl_xor_sync(0xffffffffu, s3, off);
    }
    if (lane == 0) {
        g_S[d * 4 + 0] = s0; g_S[d * 4 + 1] = s1;
        g_S[d * 4 + 2] = s2; g_S[d * 4 + 3] = s3;
    }
}

// probs[b,:] = softmax(x[b,:] @ S)
__global__ void routing_kernel(const float* __restrict__ x) {
    int gid  = blockIdx.x * blockDim.x + threadIdx.x;
    int b    = gid >> 5;
    int lane = gid & 31;
    if (b >= BATCH) return;
    const float* xr = x + (size_t)b * DMODEL;
    float s0 = 0.f, s1 = 0.f, s2 = 0.f, s3 = 0.f;
    for (int d = lane; d < DMODEL; d += 32) {
        float v = xr[d];
        float4 S4 = *(const float4*)&g_S[d * 4];
        s0 += v * S4.x; s1 += v * S4.y; s2 += v * S4.z; s3 += v * S4.w;
    }
#pragma unroll
    for (int off = 16; off; off >>= 1) {
        s0 += __shfl_xor_sync(0xffffffffu, s0, off);
        s1 += __shfl_xor_sync(0xffffffffu, s1, off);
        s2 += __shfl_xor_sync(0xffffffffu, s2, off);
        s3 += __shfl_xor_sync(0xffffffffu, s3, off);
    }
    if (lane == 0) {
        float mx = fmaxf(fmaxf(s0, s1), fmaxf(s2, s3));
        float e0 = expf(s0 - mx), e1 = expf(s1 - mx);
        float e2 = expf(s2 - mx), e3 = expf(s3 - mx);
        float inv = 1.0f / (e0 + e1 + e2 + e3);
        g_probs[b * 4 + 0] = e0 * inv;
        g_probs[b * 4 + 1] = e1 * inv;
        g_probs[b * 4 + 2] = e2 * inv;
        g_probs[b * 4 + 3] = e3 * inv;
    }
}

__global__ void reduce_col() {
    int i = blockIdx.x * blockDim.x + threadIdx.x;
    if (i >= BATCH * HD) return;
    const size_t SZ = (size_t)BATCH * HD;
    float s = g_col4[i] + g_col4[SZ + i] + g_col4[2 * SZ + i] + g_col4[3 * SZ + i];
    g_colh[i] = __float2half(s);
}

// ---------------- fp16 mma.sync m16n8k16 GEMM, z-batched -------------------
// CTA 128x128, BK=64, SW128, 3 stages. 128 threads = 4 warps (2x2), warp 64x64.
#define BM 128
#define BN 128
#define BK 64
#define STAGES 3
#define TILEB (BM * 128)
#define STAGEB (2 * TILEB)
#define GEMM_SMEM (STAGES * STAGEB)    // 98304
#define NT 128

__device__ __forceinline__ void cp16(uint32_t dst, const void* src) {
    asm volatile("cp.async.cg.shared.global [%0], [%1], 16;"
                 :: "r"(dst), "l"(src) : "memory");
}
__device__ __forceinline__ void cp_commit() {
    asm volatile("cp.async.commit_group;" ::: "memory");
}
template <int N>
__device__ __forceinline__ void cp_wait() {
    asm volatile("cp.async.wait_group %0;" :: "n"(N) : "memory");
}
__device__ __forceinline__ void ldsm4(uint32_t* r, uint32_t addr) {
    asm volatile("ldmatrix.sync.aligned.m8n8.x4.shared.b16 {%0,%1,%2,%3}, [%4];"
                 : "=r"(r[0]), "=r"(r[1]), "=r"(r[2]), "=r"(r[3]) : "r"(addr));
}
__device__ __forceinline__ void mma16816(float* c, const uint32_t* a, const uint32_t* b) {
    asm volatile(
        "mma.sync.aligned.m16n8k16.row.col.f32.f16.f16.f32 "
        "{%0,%1,%2,%3}, {%4,%5,%6,%7}, {%8,%9}, {%0,%1,%2,%3};"
        : "+f"(c[0]), "+f"(c[1]), "+f"(c[2]), "+f"(c[3])
        : "r"(a[0]), "r"(a[1]), "r"(a[2]), "r"(a[3]), "r"(b[0]), "r"(b[1]));
}

__device__ __forceinline__ float gelu_f(float v) {
    float u = 1.5957691216057308f * (v + 0.044715f * v * v * v);
    return v * (1.0f / (1.0f + __expf(-u)));
}

// EPI: 0 = plain, 1 = gelu->half, 2 = probs-scale -> fp32 partial,
//      3 = pw-row-scale -> half (Wf precompute)
template <int EPI, typename OutT>
__global__ __launch_bounds__(NT, 2)
void tgemm(const __half* __restrict__ A, const __half* __restrict__ Bt,
           OutT* __restrict__ C, int M, int N, int Kd,
           const float* __restrict__ pw,
           size_t saz, size_t sbz, size_t scz)
{
    extern __shared__ char smem[];
    uint32_t sbase = (uint32_t)__cvta_generic_to_shared(smem);

    int tid  = threadIdx.x;
    int wid  = tid >> 5;
    int lane = tid & 31;
    int g    = lane >> 2;
    int tig  = lane & 3;
    int wm   = wid & 1;        // 2 warps in M, 64 rows each
    int wn   = wid >> 1;       // 2 warps in N, 64 cols each
    int kz   = blockIdx.z;

    const __half* Ab = A  + (size_t)kz * saz + (size_t)blockIdx.y * BM * Kd;
    const __half* Bb = Bt + (size_t)kz * sbz + (size_t)blockIdx.x * BN * Kd;
    OutT* Cb = C + (size_t)kz * scz;
    int KT = Kd / BK;

    float acc[4][8][4];
#pragma unroll
    for (int i = 0; i < 4; i++)
#pragma unroll
        for (int j = 0; j < 8; j++)
#pragma unroll
            for (int q = 0; q < 4; q++) acc[i][j][q] = 0.f;

    uint32_t xm      = (uint32_t)(lane & 7) << 4;
    uint32_t a_row   = (uint32_t)(wm * 64 + (lane & 15)) * 128;
    uint32_t a_klane = (uint32_t)((lane >> 1) & 8) * 2;
    int nlo          = (lane & 7) | ((lane & 16) >> 1);
    uint32_t b_klane = (uint32_t)(lane & 8) * 2;

    auto load_stage = [&](int stage, int kt) {
        uint32_t abase = sbase + stage * STAGEB;
        uint32_t bbase = abase + TILEB;
        const __half* As = Ab + (size_t)kt * BK;
        const __half* Bs = Bb + (size_t)kt * BK;
#pragma unroll
        for (int i = 0; i < 8; i++) {
            int c   = tid + NT * i;       // 0..1023
            int row = c >> 3;
            int ch  = c & 7;
            uint32_t off = (uint32_t)row * 128 + (uint32_t)ch * 16;
            uint32_t sw  = off ^ ((off >> 3) & 0x70);
            cp16(abase + sw, As + (size_t)row * Kd + ch * 8);
            cp16(bbase + sw, Bs + (size_t)row * Kd + ch * 8);
        }
    };

#pragma unroll
    for (int s = 0; s < STAGES - 1; s++) {
        if (s < KT) load_stage(s, s);
        cp_commit();
    }

    for (int kt = 0; kt < KT; kt++) {
        cp_wait<STAGES - 2>();
        __syncthreads();   // stage kt ready; all warps past compute of kt-1

        int nxt = kt + STAGES - 1;
        if (nxt < KT) load_stage(nxt % STAGES, nxt);
        cp_commit();

        uint32_t abase = sbase + (kt % STAGES) * STAGEB;
        uint32_t bbase = abase + TILEB;

#pragma unroll
        for (int ks = 0; ks < 4; ks++) {
            uint32_t kb = (uint32_t)ks * 32;
            uint32_t af[4][4];
#pragma unroll
            for (int mf = 0; mf < 4; mf++)
                ldsm4(af[mf], abase + a_row + (uint32_t)mf * 16 * 128 +
                                ((kb + a_klane) ^ xm));
            uint32_t bf[4][4];
#pragma unroll
            for (int ng = 0; ng < 4; ng++)
                ldsm4(bf[ng], bbase + (uint32_t)(wn * 64 + ng * 16 + nlo) * 128 +
                                ((kb + b_klane) ^ xm));
#pragma unroll
            for (int mf = 0; mf < 4; mf++)
#pragma unroll
                for (int ng = 0; ng < 4; ng++) {
                    mma16816(acc[mf][2 * ng + 0], af[mf], &bf[ng][0]);
                    mma16816(acc[mf][2 * ng + 1], af[mf], &bf[ng][2]);
                }
        }
        // no trailing barrier: next iteration's leading barrier provides the
        // read-complete -> overwrite ordering for the 3-stage rotation.
    }

    // ---- epilogue ----
#pragma unroll
    for (int mf = 0; mf < 4; mf++) {
        int row0 = blockIdx.y * BM + wm * 64 + mf * 16 + g;
#pragma unroll
        for (int half = 0; half < 2; half++) {
            int row = row0 + half * 8;
            float rs = 1.f;
            if (EPI == 2) rs = g_probs[row * KPATH + kz];
            if (EPI == 3) rs = pw[kz * HD + row];
            OutT* Crow = Cb + (size_t)row * N;
#pragma unroll
            for (int nf = 0; nf < 8; nf++) {
                int col = blockIdx.x * BN + wn * 64 + (nf >> 1) * 16 + (nf & 1) * 8 + 2 * tig;
                float v0 = acc[mf][nf][half * 2 + 0];
                float v1 = acc[mf][nf][half * 2 + 1];
                if (EPI == 1) { v0 = gelu_f(v0); v1 = gelu_f(v1); }
                if (EPI == 2 || EPI == 3) { v0 *= rs; v1 *= rs; }
                if (sizeof(OutT) == 2) {
                    __half2 hv = __floats2half2_rn(v0, v1);
                    *(__half2*)((__half*)Crow + col) = hv;
                } else {
                    *(float2*)((float*)Crow + col) = make_float2(v0, v1);
                }
            }
        }
    }
}

// ---------------- launch -----------------------------------------------------
extern "C" void kernel_launch(void* const* d_in, const int* in_sizes, int n_in,
                              void* d_out, int out_size)
{
    const float* x      = (const float*)d_in[0];
    const float* c1a    = (const float*)d_in[1];
    const float* c1b    = (const float*)d_in[2];
    const float* c2a    = (const float*)d_in[3];
    const float* c2b    = (const float*)d_in[4];
    const float* hd_in  = (const float*)d_in[5];
    const float* hd_out = (const float*)d_in[6];
    const float* pb     = (const float*)d_in[7];
    const float* pw     = (const float*)d_in[8];
    float* out = (float*)d_out;

    __half *W1h, *W2n, *Wfh, *hdinTh, *hdoutTh, *xh, *h4, *colh;
    float *col4;
    cudaGetSymbolAddress((void**)&W1h,     g_W1h);
    cudaGetSymbolAddress((void**)&W2n,     g_W2n);
    cudaGetSymbolAddress((void**)&Wfh,     g_Wfh);
    cudaGetSymbolAddress((void**)&hdinTh,  g_hdinTh);
    cudaGetSymbolAddress((void**)&hdoutTh, g_hdoutTh);
    cudaGetSymbolAddress((void**)&xh,      g_xh);
    cudaGetSymbolAddress((void**)&h4,      g_h4);
    cudaGetSymbolAddress((void**)&colh,    g_colh);
    cudaGetSymbolAddress((void**)&col4,    g_col4);

    static cudaStream_t s1 = nullptr;
    static cudaEvent_t e_fork = nullptr, e_prep = nullptr, e_wf = nullptr;
    static bool attr_set = false;
    if (!attr_set) {
        cudaFuncSetAttribute(tgemm<0, float>,  cudaFuncAttributeMaxDynamicSharedMemorySize, GEMM_SMEM);
        cudaFuncSetAttribute(tgemm<1, __half>, cudaFuncAttributeMaxDynamicSharedMemorySize, GEMM_SMEM);
        cudaFuncSetAttribute(tgemm<2, float>,  cudaFuncAttributeMaxDynamicSharedMemorySize, GEMM_SMEM);
        cudaFuncSetAttribute(tgemm<3, __half>, cudaFuncAttributeMaxDynamicSharedMemorySize, GEMM_SMEM);
        cudaStreamCreateWithFlags(&s1, cudaStreamNonBlocking);
        cudaEventCreateWithFlags(&e_fork, cudaEventDisableTiming);
        cudaEventCreateWithFlags(&e_prep, cudaEventDisableTiming);
        cudaEventCreateWithFlags(&e_wf,   cudaEventDisableTiming);
        attr_set = true;
    }

    // ---- fork side stream s1 into the (captured) main stream's graph ----
    cudaEventRecord(e_fork, 0);
    cudaStreamWaitEvent(s1, e_fork, 0);

    // s1: W2n -> S -> routing (independent of GEMM1's inputs)
    build_w2n<<<(KPATH * DFF * DMODEL + 255) / 256, 256, 0, s1>>>(c2a, c2b);
    build_S<<<(DMODEL * 32 + 255) / 256, 256, 0, s1>>>(hd_in, pb);
    routing_kernel<<<(BATCH * 32 + 255) / 256, 256, 0, s1>>>(x);

    // main stream: W1h, prep (xh / hdinTh / hdoutTh)
    build_w1h<<<(KPATH * DFF * DMODEL + 255) / 256, 256>>>(c1a, c1b);
    prep<<<2048, 256>>>(x, hd_in, hd_out);
    cudaEventRecord(e_prep, 0);
    cudaStreamWaitEvent(s1, e_prep, 0);    // Wf needs hdinTh from prep

    // s1: folded tail weights WfT_k[512,4096] = (hd_inT @ W2_k^T) * pw_k(row)
    tgemm<3, __half><<<dim3(DFF / BN, HD / BM, KPATH), NT, GEMM_SMEM, s1>>>(
        hdinTh, W2n, Wfh, HD, DFF, DMODEL, pw,
        0, (size_t)DFF * DMODEL, (size_t)HD * DFF);
    cudaEventRecord(e_wf, s1);

    // main: GEMM1 h_k = gelu(x @ W1_k) — overlaps the whole s1 chain
    tgemm<1, __half><<<dim3(DFF / BN, BATCH / BM, KPATH), NT, GEMM_SMEM>>>(
        xh, W1h, h4, BATCH, DFF, DMODEL, nullptr,
        0, (size_t)DFF * DMODEL, (size_t)BATCH * DFF);

    // join: tail needs h4 (main) + Wfh, probs (s1)
    cudaStreamWaitEvent(0, e_wf, 0);

    // main: col4_k = probs[:,k] * (h_k @ Wf_k)
    tgemm<2, float><<<dim3(HD / BN, BATCH / BM, KPATH), NT, GEMM_SMEM>>>(
        h4, Wfh, col4, BATCH, HD, DFF, nullptr,
        (size_t)BATCH * DFF, (size_t)HD * DFF, (size_t)BATCH * HD);

    // main: reduce partials -> colh (fp16)
    reduce_col<<<(BATCH * HD + 255) / 256, 256>>>();

    // main: out = col @ hd_out (fp32)
    tgemm<0, float><<<dim3(DMODEL / BN, BATCH / BM, 1), NT, GEMM_SMEM>>>(
        colh, hdoutTh, out, BATCH, DMODEL, HD, nullptr, 0, 0, 0);
}

// round 16
// speedup vs baseline: 1.5883x; 1.5218x over previous
#include <cuda_runtime.h>
#include <cuda_fp16.h>
#include <math.h>
#include <stdint.h>

// Problem constants
#define BATCH   8192
#define DMODEL  1024
#define DFF     4096
#define KPATH   4
#define RANK    16
#define HD      512

// ---------------- scratch (device globals; no allocation allowed) ----------
__device__ __half g_W1h[KPATH * DFF * DMODEL];   // [k][4096][1024] (N,K) 32MB
__device__ __half g_W2n[KPATH * DFF * DMODEL];   // [k][4096][1024] natural 32MB
__device__ __half g_Wfh[KPATH * HD * DFF];       // [k][512][4096] 16MB
__device__ __half g_hdinTh[HD * DMODEL];
__device__ __half g_hdoutTh[DMODEL * HD];
__device__ __half g_xh[BATCH * DMODEL];          // 16MB
__device__ __half g_h4[(size_t)KPATH * BATCH * DFF];   // 256MB
__device__ float  g_col4[(size_t)KPATH * BATCH * HD];  // 64MB
__device__ __half g_colh[BATCH * HD];            // 8MB
__device__ float  g_S[DMODEL * KPATH];           // routing mat [1024][4]
__device__ float  g_probs[BATCH * KPATH];

// ---------------- builders (smem-tiled; was 903us LSU-bound each) -----------
// W1T[k][nn=n*64+o][d=m*32+p] = sum_r c1a[k,m,n,r] * c1b[k,r,p,o]
// block = (k, m, n); p in 0..31, o in 0..63; thread: o=t>>2, 8 p's.
__global__ __launch_bounds__(256)
void build_w1h(const float* __restrict__ c1a, const float* __restrict__ c1b) {
    __shared__ float sa[16];
    __shared__ float sb[4][32][65];    // [r-chunk][p][o pad] bank=(p+o)%32
    int k = blockIdx.y;
    int m = blockIdx.x >> 6;           // 0..31
    int n = blockIdx.x & 63;           // 0..63
    int t = threadIdx.x;
    if (t < 16) sa[t] = c1a[(((k * 32 + m) * 64 + n) << 4) + t];
    int o  = t >> 2;                   // 0..63
    int pb = (t & 3) * 8;              // 0,8,16,24
    float acc[8];
#pragma unroll
    for (int j = 0; j < 8; j++) acc[j] = 0.f;
    const float* bbase = c1b + (size_t)k * 32768;   // [r=16][p=32][o=64]
    for (int rc = 0; rc < 4; rc++) {
        __syncthreads();
        const float* src = bbase + rc * 8192;
#pragma unroll
        for (int jj = 0; jj < 8; jj++) {
            int e = (t + 256 * jj) * 4;
            float4 v = *(const float4*)(src + e);
            int ri = e >> 11, rem = e & 2047;
            int pp = rem >> 6, oo = rem & 63;
            sb[ri][pp][oo + 0] = v.x;
            sb[ri][pp][oo + 1] = v.y;
            sb[ri][pp][oo + 2] = v.z;
            sb[ri][pp][oo + 3] = v.w;
        }
        __syncthreads();
#pragma unroll
        for (int i = 0; i < 4; i++) {
            float ar = sa[rc * 4 + i];
#pragma unroll
            for (int j = 0; j < 8; j++)
                acc[j] += ar * sb[i][pb + j][o];
        }
    }
    __half hv[8];
#pragma unroll
    for (int j = 0; j < 8; j++) hv[j] = __float2half(acc[j]);
    size_t base = (((size_t)k * DFF) + n * 64 + o) * DMODEL + m * 32 + pb;
    *(uint4*)&g_W1h[base] = *(uint4*)hv;
}

// W2n[k][ff=m*64+p][dm=n*32+o] = sum_r c2a[k,m,n,r] * c2b[k,r,p,o]
// block = (k, m, n); p in 0..63, o in 0..31; thread: p=t>>2, 8 o's.
__global__ __launch_bounds__(256)
void build_w2n(const float* __restrict__ c2a, const float* __restrict__ c2b) {
    __shared__ float sa[16];
    __shared__ float sb[4][64][33];    // bank=(p+o)%32
    int k = blockIdx.y;
    int m = blockIdx.x >> 5;           // 0..63
    int n = blockIdx.x & 31;           // 0..31
    int t = threadIdx.x;
    if (t < 16) sa[t] = c2a[(((k * 64 + m) * 32 + n) << 4) + t];
    int p  = t >> 2;                   // 0..63
    int ob = (t & 3) * 8;              // 0,8,16,24
    float acc[8];
#pragma unroll
    for (int j = 0; j < 8; j++) acc[j] = 0.f;
    const float* bbase = c2b + (size_t)k * 32768;   // [r=16][p=64][o=32]
    for (int rc = 0; rc < 4; rc++) {
        __syncthreads();
        const float* src = bbase + rc * 8192;
#pragma unroll
        for (int jj = 0; jj < 8; jj++) {
            int e = (t + 256 * jj) * 4;
            float4 v = *(const float4*)(src + e);
            int ri = e >> 11, rem = e & 2047;
            int pp = rem >> 5, oo = rem & 31;
            sb[ri][pp][oo + 0] = v.x;
            sb[ri][pp][oo + 1] = v.y;
            sb[ri][pp][oo + 2] = v.z;
            sb[ri][pp][oo + 3] = v.w;
        }
        __syncthreads();
#pragma unroll
        for (int i = 0; i < 4; i++) {
            float ar = sa[rc * 4 + i];
#pragma unroll
            for (int j = 0; j < 8; j++)
                acc[j] += ar * sb[i][p][ob + j];
        }
    }
    __half hv[8];
#pragma unroll
    for (int j = 0; j < 8; j++) hv[j] = __float2half(acc[j]);
    size_t base = (((size_t)k * DFF) + m * 64 + p) * DMODEL + n * 32 + ob;
    *(uint4*)&g_W2n[base] = *(uint4*)hv;
}

// merged: x->fp16, hd_in transpose->fp16, hd_out transpose->fp16
#define PREP_N1 (BATCH * DMODEL)
#define PREP_N2 (DMODEL * HD)
#define PREP_TOT (PREP_N1 + 2 * PREP_N2)
__global__ void prep(const float* __restrict__ x,
                     const float* __restrict__ hd_in,
                     const float* __restrict__ hd_out) {
    for (int i = blockIdx.x * blockDim.x + threadIdx.x; i < PREP_TOT;
         i += gridDim.x * blockDim.x) {
        if (i < PREP_N1) {
            g_xh[i] = __float2half(x[i]);
        } else if (i < PREP_N1 + PREP_N2) {
            int j = i - PREP_N1;
            int d = j / HD, h2 = j % HD;
            g_hdinTh[(size_t)h2 * DMODEL + d] = __float2half(hd_in[j]);
        } else {
            int j = i - PREP_N1 - PREP_N2;
            int h2 = j / DMODEL, d = j % DMODEL;
            g_hdoutTh[(size_t)d * HD + h2] = __float2half(hd_out[j]);
        }
    }
}

// S[d][k] = sum_h hd_in[d,h] * pb[k,h]
__global__ void build_S(const float* __restrict__ hd_in, const float* __restrict__ pb) {
    int gid  = blockIdx.x * blockDim.x + threadIdx.x;
    int d    = gid >> 5;
    int lane = gid & 31;
    if (d >= DMODEL) return;
    const float* hr = hd_in + (size_t)d * HD;
    float s0 = 0.f, s1 = 0.f, s2 = 0.f, s3 = 0.f;
    for (int h = lane; h < HD; h += 32) {
        float v = hr[h];
        s0 += v * pb[0 * HD + h];
        s1 += v * pb[1 * HD + h];
        s2 += v * pb[2 * HD + h];
        s3 += v * pb[3 * HD + h];
    }
#pragma unroll
    for (int off = 16; off; off >>= 1) {
        s0 += __shfl_xor_sync(0xffffffffu, s0, off);
        s1 += __shfl_xor_sync(0xffffffffu, s1, off);
        s2 += __shfl_xor_sync(0xffffffffu, s2, off);
        s3 += __shfl_xor_sync(0xffffffffu, s3, off);
    }
    if (lane == 0) {
        g_S[d * 4 + 0] = s0; g_S[d * 4 + 1] = s1;
        g_S[d * 4 + 2] = s2; g_S[d * 4 + 3] = s3;
    }
}

// probs[b,:] = softmax(x[b,:] @ S)
__global__ void routing_kernel(const float* __restrict__ x) {
    int gid  = blockIdx.x * blockDim.x + threadIdx.x;
    int b    = gid >> 5;
    int lane = gid & 31;
    if (b >= BATCH) return;
    const float* xr = x + (size_t)b * DMODEL;
    float s0 = 0.f, s1 = 0.f, s2 = 0.f, s3 = 0.f;
    for (int d = lane; d < DMODEL; d += 32) {
        float v = xr[d];
        float4 S4 = *(const float4*)&g_S[d * 4];
        s0 += v * S4.x; s1 += v * S4.y; s2 += v * S4.z; s3 += v * S4.w;
    }
#pragma unroll
    for (int off = 16; off; off >>= 1) {
        s0 += __shfl_xor_sync(0xffffffffu, s0, off);
        s1 += __shfl_xor_sync(0xffffffffu, s1, off);
        s2 += __shfl_xor_sync(0xffffffffu, s2, off);
        s3 += __shfl_xor_sync(0xffffffffu, s3, off);
    }
    if (lane == 0) {
        float mx = fmaxf(fmaxf(s0, s1), fmaxf(s2, s3));
        float e0 = expf(s0 - mx), e1 = expf(s1 - mx);
        float e2 = expf(s2 - mx), e3 = expf(s3 - mx);
        float inv = 1.0f / (e0 + e1 + e2 + e3);
        g_probs[b * 4 + 0] = e0 * inv;
        g_probs[b * 4 + 1] = e1 * inv;
        g_probs[b * 4 + 2] = e2 * inv;
        g_probs[b * 4 + 3] = e3 * inv;
    }
}

__global__ void reduce_col() {
    int i = blockIdx.x * blockDim.x + threadIdx.x;
    if (i >= BATCH * HD) return;
    const size_t SZ = (size_t)BATCH * HD;
    float s = g_col4[i] + g_col4[SZ + i] + g_col4[2 * SZ + i] + g_col4[3 * SZ + i];
    g_colh[i] = __float2half(s);
}

// ---------------- fp16 mma.sync m16n8k16 GEMM, z-batched -------------------
#define BM 128
#define BN 128
#define BK 64
#define STAGES 3
#define TILEB (BM * 128)
#define STAGEB (2 * TILEB)
#define GEMM_SMEM (STAGES * STAGEB)    // 98304
#define NT 128

__device__ __forceinline__ void cp16(uint32_t dst, const void* src) {
    asm volatile("cp.async.cg.shared.global [%0], [%1], 16;"
                 :: "r"(dst), "l"(src) : "memory");
}
__device__ __forceinline__ void cp_commit() {
    asm volatile("cp.async.commit_group;" ::: "memory");
}
template <int N>
__device__ __forceinline__ void cp_wait() {
    asm volatile("cp.async.wait_group %0;" :: "n"(N) : "memory");
}
__device__ __forceinline__ void ldsm4(uint32_t* r, uint32_t addr) {
    asm volatile("ldmatrix.sync.aligned.m8n8.x4.shared.b16 {%0,%1,%2,%3}, [%4];"
                 : "=r"(r[0]), "=r"(r[1]), "=r"(r[2]), "=r"(r[3]) : "r"(addr));
}
__device__ __forceinline__ void mma16816(float* c, const uint32_t* a, const uint32_t* b) {
    asm volatile(
        "mma.sync.aligned.m16n8k16.row.col.f32.f16.f16.f32 "
        "{%0,%1,%2,%3}, {%4,%5,%6,%7}, {%8,%9}, {%0,%1,%2,%3};"
        : "+f"(c[0]), "+f"(c[1]), "+f"(c[2]), "+f"(c[3])
        : "r"(a[0]), "r"(a[1]), "r"(a[2]), "r"(a[3]), "r"(b[0]), "r"(b[1]));
}

__device__ __forceinline__ float gelu_f(float v) {
    float u = 1.5957691216057308f * (v + 0.044715f * v * v * v);
    return v * (1.0f / (1.0f + __expf(-u)));
}

// EPI: 0 = plain, 1 = gelu->half, 2 = probs-scale -> fp32 partial,
//      3 = pw-row-scale -> half (Wf precompute)
template <int EPI, typename OutT>
__global__ __launch_bounds__(NT, 2)
void tgemm(const __half* __restrict__ A, const __half* __restrict__ Bt,
           OutT* __restrict__ C, int M, int N, int Kd,
           const float* __restrict__ pw,
           size_t saz, size_t sbz, size_t scz)
{
    extern __shared__ char smem[];
    uint32_t sbase = (uint32_t)__cvta_generic_to_shared(smem);

    int tid  = threadIdx.x;
    int wid  = tid >> 5;
    int lane = tid & 31;
    int g    = lane >> 2;
    int tig  = lane & 3;
    int wm   = wid & 1;
    int wn   = wid >> 1;
    int kz   = blockIdx.z;

    const __half* Ab = A  + (size_t)kz * saz + (size_t)blockIdx.y * BM * Kd;
    const __half* Bb = Bt + (size_t)kz * sbz + (size_t)blockIdx.x * BN * Kd;
    OutT* Cb = C + (size_t)kz * scz;
    int KT = Kd / BK;

    float acc[4][8][4];
#pragma unroll
    for (int i = 0; i < 4; i++)
#pragma unroll
        for (int j = 0; j < 8; j++)
#pragma unroll
            for (int q = 0; q < 4; q++) acc[i][j][q] = 0.f;

    uint32_t xm      = (uint32_t)(lane & 7) << 4;
    uint32_t a_row   = (uint32_t)(wm * 64 + (lane & 15)) * 128;
    uint32_t a_klane = (uint32_t)((lane >> 1) & 8) * 2;
    int nlo          = (lane & 7) | ((lane & 16) >> 1);
    uint32_t b_klane = (uint32_t)(lane & 8) * 2;

    auto load_stage = [&](int stage, int kt) {
        uint32_t abase = sbase + stage * STAGEB;
        uint32_t bbase = abase + TILEB;
        const __half* As = Ab + (size_t)kt * BK;
        const __half* Bs = Bb + (size_t)kt * BK;
#pragma unroll
        for (int i = 0; i < 8; i++) {
            int c   = tid + NT * i;
            int row = c >> 3;
            int ch  = c & 7;
            uint32_t off = (uint32_t)row * 128 + (uint32_t)ch * 16;
            uint32_t sw  = off ^ ((off >> 3) & 0x70);
            cp16(abase + sw, As + (size_t)row * Kd + ch * 8);
            cp16(bbase + sw, Bs + (size_t)row * Kd + ch * 8);
        }
    };

#pragma unroll
    for (int s = 0; s < STAGES - 1; s++) {
        if (s < KT) load_stage(s, s);
        cp_commit();
    }

    for (int kt = 0; kt < KT; kt++) {
        cp_wait<STAGES - 2>();
        __syncthreads();

        int nxt = kt + STAGES - 1;
        if (nxt < KT) load_stage(nxt % STAGES, nxt);
        cp_commit();

        uint32_t abase = sbase + (kt % STAGES) * STAGEB;
        uint32_t bbase = abase + TILEB;

#pragma unroll
        for (int ks = 0; ks < 4; ks++) {
            uint32_t kb = (uint32_t)ks * 32;
            uint32_t af[4][4];
#pragma unroll
            for (int mf = 0; mf < 4; mf++)
                ldsm4(af[mf], abase + a_row + (uint32_t)mf * 16 * 128 +
                                ((kb + a_klane) ^ xm));
            uint32_t bf[4][4];
#pragma unroll
            for (int ng = 0; ng < 4; ng++)
                ldsm4(bf[ng], bbase + (uint32_t)(wn * 64 + ng * 16 + nlo) * 128 +
                                ((kb + b_klane) ^ xm));
#pragma unroll
            for (int mf = 0; mf < 4; mf++)
#pragma unroll
                for (int ng = 0; ng < 4; ng++) {
                    mma16816(acc[mf][2 * ng + 0], af[mf], &bf[ng][0]);
                    mma16816(acc[mf][2 * ng + 1], af[mf], &bf[ng][2]);
                }
        }
    }

    // ---- epilogue ----
#pragma unroll
    for (int mf = 0; mf < 4; mf++) {
        int row0 = blockIdx.y * BM + wm * 64 + mf * 16 + g;
#pragma unroll
        for (int half = 0; half < 2; half++) {
            int row = row0 + half * 8;
            float rs = 1.f;
            if (EPI == 2) rs = g_probs[row * KPATH + kz];
            if (EPI == 3) rs = pw[kz * HD + row];
            OutT* Crow = Cb + (size_t)row * N;
#pragma unroll
            for (int nf = 0; nf < 8; nf++) {
                int col = blockIdx.x * BN + wn * 64 + (nf >> 1) * 16 + (nf & 1) * 8 + 2 * tig;
                float v0 = acc[mf][nf][half * 2 + 0];
                float v1 = acc[mf][nf][half * 2 + 1];
                if (EPI == 1) { v0 = gelu_f(v0); v1 = gelu_f(v1); }
                if (EPI == 2 || EPI == 3) { v0 *= rs; v1 *= rs; }
                if (sizeof(OutT) == 2) {
                    __half2 hv = __floats2half2_rn(v0, v1);
                    *(__half2*)((__half*)Crow + col) = hv;
                } else {
                    *(float2*)((float*)Crow + col) = make_float2(v0, v1);
                }
            }
        }
    }
}

// ---------------- launch -----------------------------------------------------
extern "C" void kernel_launch(void* const* d_in, const int* in_sizes, int n_in,
                              void* d_out, int out_size)
{
    const float* x      = (const float*)d_in[0];
    const float* c1a    = (const float*)d_in[1];
    const float* c1b    = (const float*)d_in[2];
    const float* c2a    = (const float*)d_in[3];
    const float* c2b    = (const float*)d_in[4];
    const float* hd_in  = (const float*)d_in[5];
    const float* hd_out = (const float*)d_in[6];
    const float* pb     = (const float*)d_in[7];
    const float* pw     = (const float*)d_in[8];
    float* out = (float*)d_out;

    __half *W1h, *W2n, *Wfh, *hdinTh, *hdoutTh, *xh, *h4, *colh;
    float *col4;
    cudaGetSymbolAddress((void**)&W1h,     g_W1h);
    cudaGetSymbolAddress((void**)&W2n,     g_W2n);
    cudaGetSymbolAddress((void**)&Wfh,     g_Wfh);
    cudaGetSymbolAddress((void**)&hdinTh,  g_hdinTh);
    cudaGetSymbolAddress((void**)&hdoutTh, g_hdoutTh);
    cudaGetSymbolAddress((void**)&xh,      g_xh);
    cudaGetSymbolAddress((void**)&h4,      g_h4);
    cudaGetSymbolAddress((void**)&colh,    g_colh);
    cudaGetSymbolAddress((void**)&col4,    g_col4);

    static cudaStream_t s1 = nullptr;
    static cudaEvent_t e_fork = nullptr, e_prep = nullptr, e_wf = nullptr;
    static bool attr_set = false;
    if (!attr_set) {
        cudaFuncSetAttribute(tgemm<0, float>,  cudaFuncAttributeMaxDynamicSharedMemorySize, GEMM_SMEM);
        cudaFuncSetAttribute(tgemm<1, __half>, cudaFuncAttributeMaxDynamicSharedMemorySize, GEMM_SMEM);
        cudaFuncSetAttribute(tgemm<2, float>,  cudaFuncAttributeMaxDynamicSharedMemorySize, GEMM_SMEM);
        cudaFuncSetAttribute(tgemm<3, __half>, cudaFuncAttributeMaxDynamicSharedMemorySize, GEMM_SMEM);
        cudaStreamCreateWithFlags(&s1, cudaStreamNonBlocking);
        cudaEventCreateWithFlags(&e_fork, cudaEventDisableTiming);
        cudaEventCreateWithFlags(&e_prep, cudaEventDisableTiming);
        cudaEventCreateWithFlags(&e_wf,   cudaEventDisableTiming);
        attr_set = true;
    }

    // ---- fork side stream s1 into the (captured) main stream's graph ----
    cudaEventRecord(e_fork, 0);
    cudaStreamWaitEvent(s1, e_fork, 0);

    // s1: W2n -> S -> routing (independent of GEMM1's inputs)
    build_w2n<<<dim3(2048, KPATH), 256, 0, s1>>>(c2a, c2b);
    build_S<<<(DMODEL * 32 + 255) / 256, 256, 0, s1>>>(hd_in, pb);
    routing_kernel<<<(BATCH * 32 + 255) / 256, 256, 0, s1>>>(x);

    // main stream: W1h, prep (xh / hdinTh / hdoutTh)
    build_w1h<<<dim3(2048, KPATH), 256>>>(c1a, c1b);
    prep<<<2048, 256>>>(x, hd_in, hd_out);
    cudaEventRecord(e_prep, 0);
    cudaStreamWaitEvent(s1, e_prep, 0);    // Wf needs hdinTh from prep

    // s1: folded tail weights WfT_k[512,4096] = (hd_inT @ W2_k^T) * pw_k(row)
    tgemm<3, __half><<<dim3(DFF / BN, HD / BM, KPATH), NT, GEMM_SMEM, s1>>>(
        hdinTh, W2n, Wfh, HD, DFF, DMODEL, pw,
        0, (size_t)DFF * DMODEL, (size_t)HD * DFF);
    cudaEventRecord(e_wf, s1);

    // main: GEMM1 h_k = gelu(x @ W1_k) — overlaps the s1 chain
    tgemm<1, __half><<<dim3(DFF / BN, BATCH / BM, KPATH), NT, GEMM_SMEM>>>(
        xh, W1h, h4, BATCH, DFF, DMODEL, nullptr,
        0, (size_t)DFF * DMODEL, (size_t)BATCH * DFF);

    // join: tail needs h4 (main) + Wfh, probs (s1)
    cudaStreamWaitEvent(0, e_wf, 0);

    // main: col4_k = probs[:,k] * (h_k @ Wf_k)
    tgemm<2, float><<<dim3(HD / BN, BATCH / BM, KPATH), NT, GEMM_SMEM>>>(
        h4, Wfh, col4, BATCH, HD, DFF, nullptr,
        (size_t)BATCH * DFF, (size_t)HD * DFF, (size_t)BATCH * HD);

    // main: reduce partials -> colh (fp16)
    reduce_col<<<(BATCH * HD + 255) / 256, 256>>>();

    // main: out = col @ hd_out (fp32)
    tgemm<0, float><<<dim3(DMODEL / BN, BATCH / BM, 1), NT, GEMM_SMEM>>>(
        colh, hdoutTh, out, BATCH, DMODEL, HD, nullptr, 0, 0, 0);
}

// round 17
// speedup vs baseline: 1.8521x; 1.1661x over previous
#include <cuda_runtime.h>
#include <cuda_fp16.h>
#include <math.h>
#include <stdint.h>

// Problem constants
#define BATCH   8192
#define DMODEL  1024
#define DFF     4096
#define KPATH   4
#define RANK    16
#define HD      512

// ---------------- scratch (device globals; no allocation allowed) ----------
__device__ __half g_W1h[KPATH * DFF * DMODEL];   // [k][4096][1024] (N,K) 32MB
__device__ __half g_W2n[KPATH * DFF * DMODEL];   // [k][4096][1024] natural 32MB
__device__ __half g_Wfh[KPATH * HD * DFF];       // [k][512][4096] 16MB
__device__ __half g_hdinTh[HD * DMODEL];
__device__ __half g_hdoutTh[DMODEL * HD];
__device__ __half g_xh[BATCH * DMODEL];          // 16MB
__device__ __half g_h4[(size_t)KPATH * BATCH * DFF];   // 256MB
__device__ float  g_col4[(size_t)KPATH * BATCH * HD];  // 64MB
__device__ __half g_colh[BATCH * HD];            // 8MB
__device__ float  g_S[DMODEL * KPATH];           // routing mat [1024][4]
__device__ float  g_probs[BATCH * KPATH];

// ---------------- builders v3: B held in registers, FMA-bound --------------
// W1T[k][nn=n*64+o][d=m*32+p] = sum_r c1a[k,m,n,r] * c1b[k,r,p,o]
// block = (k, m, nh); thread owns (o, 4 p's): breg[16][4] invariant over n.
__global__ __launch_bounds__(512)
void build_w1h(const float* __restrict__ c1a, const float* __restrict__ c1b) {
    __shared__ float sa[32][16];       // c1a[k,m, nh*32+n, r]
    int k  = blockIdx.y;
    int m  = blockIdx.x >> 1;          // 0..31
    int nh = blockIdx.x & 1;           // 0..1
    int t  = threadIdx.x;              // 0..511
    int o  = t >> 3;                   // 0..63
    int p4 = (t & 7) * 4;              // 0,4,...,28

    {   // load c1a slice: 512 entries, one per thread
        int n = t >> 4, r = t & 15;
        sa[n][r] = c1a[(((k * 32 + m) * 64 + nh * 32 + n) << 4) + r];
    }
    // hoist c1b[r, p4..p4+4, o] into registers (invariant over n, m)
    float breg[16][4];
    const float* bbase = c1b + (size_t)k * 32768;   // [r=16][p=32][o=64]
#pragma unroll
    for (int r = 0; r < 16; r++)
#pragma unroll
        for (int j = 0; j < 4; j++)
            breg[r][j] = bbase[r * 2048 + (p4 + j) * 64 + o];
    __syncthreads();

    size_t rowbase = ((size_t)k * DFF + nh * 2048 + o) * DMODEL + m * 32 + p4;
    for (int n = 0; n < 32; n++) {
        float a[16];
#pragma unroll
        for (int r = 0; r < 16; r++) a[r] = sa[n][r];   // broadcast LDS
        float acc[4] = {0.f, 0.f, 0.f, 0.f};
#pragma unroll
        for (int r = 0; r < 16; r++)
#pragma unroll
            for (int j = 0; j < 4; j++)
                acc[j] += a[r] * breg[r][j];
        __half hv[4];
#pragma unroll
        for (int j = 0; j < 4; j++) hv[j] = __float2half(acc[j]);
        *(uint2*)&g_W1h[rowbase + (size_t)n * 64 * DMODEL] = *(uint2*)hv;
    }
}

// W2n[k][ff=m*64+p][dm=n*32+o] = sum_r c2a[k,m,n,r] * c2b[k,r,p,o]
// block = (k, m); thread owns (p, 4 o's): breg via float4 (o contiguous).
__global__ __launch_bounds__(512)
void build_w2n(const float* __restrict__ c2a, const float* __restrict__ c2b) {
    __shared__ float sa[32][16];       // c2a[k,m,n,r]
    int k  = blockIdx.y;
    int m  = blockIdx.x;               // 0..63
    int t  = threadIdx.x;              // 0..511
    int p  = t >> 3;                   // 0..63
    int o4 = (t & 7) * 4;              // 0,4,...,28

    {   // load c2a slice: 512 entries
        int n = t >> 4, r = t & 15;
        sa[n][r] = c2a[(((k * 64 + m) * 32 + n) << 4) + r];
    }
    float breg[16][4];
    const float* bbase = c2b + (size_t)k * 32768;   // [r=16][p=64][o=32]
#pragma unroll
    for (int r = 0; r < 16; r++) {
        float4 v = *(const float4*)(bbase + r * 2048 + p * 32 + o4);
        breg[r][0] = v.x; breg[r][1] = v.y; breg[r][2] = v.z; breg[r][3] = v.w;
    }
    __syncthreads();

    size_t rowbase = ((size_t)k * DFF + m * 64 + p) * DMODEL + o4;
    for (int n = 0; n < 32; n++) {
        float a[16];
#pragma unroll
        for (int r = 0; r < 16; r++) a[r] = sa[n][r];
        float acc[4] = {0.f, 0.f, 0.f, 0.f};
#pragma unroll
        for (int r = 0; r < 16; r++)
#pragma unroll
            for (int j = 0; j < 4; j++)
                acc[j] += a[r] * breg[r][j];
        __half hv[4];
#pragma unroll
        for (int j = 0; j < 4; j++) hv[j] = __float2half(acc[j]);
        *(uint2*)&g_W2n[rowbase + (size_t)n * 32] = *(uint2*)hv;
    }
}

// merged: x->fp16, hd_in transpose->fp16, hd_out transpose->fp16
#define PREP_N1 (BATCH * DMODEL)
#define PREP_N2 (DMODEL * HD)
#define PREP_TOT (PREP_N1 + 2 * PREP_N2)
__global__ void prep(const float* __restrict__ x,
                     const float* __restrict__ hd_in,
                     const float* __restrict__ hd_out) {
    for (int i = blockIdx.x * blockDim.x + threadIdx.x; i < PREP_TOT;
         i += gridDim.x * blockDim.x) {
        if (i < PREP_N1) {
            g_xh[i] = __float2half(x[i]);
        } else if (i < PREP_N1 + PREP_N2) {
            int j = i - PREP_N1;
            int d = j / HD, h2 = j % HD;
            g_hdinTh[(size_t)h2 * DMODEL + d] = __float2half(hd_in[j]);
        } else {
            int j = i - PREP_N1 - PREP_N2;
            int h2 = j / DMODEL, d = j % DMODEL;
            g_hdoutTh[(size_t)d * HD + h2] = __float2half(hd_out[j]);
        }
    }
}

// S[d][k] = sum_h hd_in[d,h] * pb[k,h]
__global__ void build_S(const float* __restrict__ hd_in, const float* __restrict__ pb) {
    int gid  = blockIdx.x * blockDim.x + threadIdx.x;
    int d    = gid >> 5;
    int lane = gid & 31;
    if (d >= DMODEL) return;
    const float* hr = hd_in + (size_t)d * HD;
    float s0 = 0.f, s1 = 0.f, s2 = 0.f, s3 = 0.f;
    for (int h = lane; h < HD; h += 32) {
        float v = hr[h];
        s0 += v * pb[0 * HD + h];
        s1 += v * pb[1 * HD + h];
        s2 += v * pb[2 * HD + h];
        s3 += v * pb[3 * HD + h];
    }
#pragma unroll
    for (int off = 16; off; off >>= 1) {
        s0 += __shfl_xor_sync(0xffffffffu, s0, off);
        s1 += __shfl_xor_sync(0xffffffffu, s1, off);
        s2 += __shfl_xor_sync(0xffffffffu, s2, off);
        s3 += __shfl_xor_sync(0xffffffffu, s3, off);
    }
    if (lane == 0) {
        g_S[d * 4 + 0] = s0; g_S[d * 4 + 1] = s1;
        g_S[d * 4 + 2] = s2; g_S[d * 4 + 3] = s3;
    }
}

// probs[b,:] = softmax(x[b,:] @ S)
__global__ void routing_kernel(const float* __restrict__ x) {
    int gid  = blockIdx.x * blockDim.x + threadIdx.x;
    int b    = gid >> 5;
    int lane = gid & 31;
    if (b >= BATCH) return;
    const float* xr = x + (size_t)b * DMODEL;
    float s0 = 0.f, s1 = 0.f, s2 = 0.f, s3 = 0.f;
    for (int d = lane; d < DMODEL; d += 32) {
        float v = xr[d];
        float4 S4 = *(const float4*)&g_S[d * 4];
        s0 += v * S4.x; s1 += v * S4.y; s2 += v * S4.z; s3 += v * S4.w;
    }
#pragma unroll
    for (int off = 16; off; off >>= 1) {
        s0 += __shfl_xor_sync(0xffffffffu, s0, off);
        s1 += __shfl_xor_sync(0xffffffffu, s1, off);
        s2 += __shfl_xor_sync(0xffffffffu, s2, off);
        s3 += __shfl_xor_sync(0xffffffffu, s3, off);
    }
    if (lane == 0) {
        float mx = fmaxf(fmaxf(s0, s1), fmaxf(s2, s3));
        float e0 = expf(s0 - mx), e1 = expf(s1 - mx);
        float e2 = expf(s2 - mx), e3 = expf(s3 - mx);
        float inv = 1.0f / (e0 + e1 + e2 + e3);
        g_probs[b * 4 + 0] = e0 * inv;
        g_probs[b * 4 + 1] = e1 * inv;
        g_probs[b * 4 + 2] = e2 * inv;
        g_probs[b * 4 + 3] = e3 * inv;
    }
}

__global__ void reduce_col() {
    int i = blockIdx.x * blockDim.x + threadIdx.x;
    if (i >= BATCH * HD) return;
    const size_t SZ = (size_t)BATCH * HD;
    float s = g_col4[i] + g_col4[SZ + i] + g_col4[2 * SZ + i] + g_col4[3 * SZ + i];
    g_colh[i] = __float2half(s);
}

// ---------------- fp16 mma.sync m16n8k16 GEMM, z-batched -------------------
#define BM 128
#define BN 128
#define BK 64
#define STAGES 3
#define TILEB (BM * 128)
#define STAGEB (2 * TILEB)
#define GEMM_SMEM (STAGES * STAGEB)    // 98304
#define NT 128

__device__ __forceinline__ void cp16(uint32_t dst, const void* src) {
    asm volatile("cp.async.cg.shared.global [%0], [%1], 16;"
                 :: "r"(dst), "l"(src) : "memory");
}
__device__ __forceinline__ void cp_commit() {
    asm volatile("cp.async.commit_group;" ::: "memory");
}
template <int N>
__device__ __forceinline__ void cp_wait() {
    asm volatile("cp.async.wait_group %0;" :: "n"(N) : "memory");
}
__device__ __forceinline__ void ldsm4(uint32_t* r, uint32_t addr) {
    asm volatile("ldmatrix.sync.aligned.m8n8.x4.shared.b16 {%0,%1,%2,%3}, [%4];"
                 : "=r"(r[0]), "=r"(r[1]), "=r"(r[2]), "=r"(r[3]) : "r"(addr));
}
__device__ __forceinline__ void mma16816(float* c, const uint32_t* a, const uint32_t* b) {
    asm volatile(
        "mma.sync.aligned.m16n8k16.row.col.f32.f16.f16.f32 "
        "{%0,%1,%2,%3}, {%4,%5,%6,%7}, {%8,%9}, {%0,%1,%2,%3};"
        : "+f"(c[0]), "+f"(c[1]), "+f"(c[2]), "+f"(c[3])
        : "r"(a[0]), "r"(a[1]), "r"(a[2]), "r"(a[3]), "r"(b[0]), "r"(b[1]));
}

__device__ __forceinline__ float gelu_f(float v) {
    float u = 1.5957691216057308f * (v + 0.044715f * v * v * v);
    return v * (1.0f / (1.0f + __expf(-u)));
}

// EPI: 0 = plain, 1 = gelu->half, 2 = probs-scale -> fp32 partial,
//      3 = pw-row-scale -> half (Wf precompute)
template <int EPI, typename OutT>
__global__ __launch_bounds__(NT, 2)
void tgemm(const __half* __restrict__ A, const __half* __restrict__ Bt,
           OutT* __restrict__ C, int M, int N, int Kd,
           const float* __restrict__ pw,
           size_t saz, size_t sbz, size_t scz)
{
    extern __shared__ char smem[];
    uint32_t sbase = (uint32_t)__cvta_generic_to_shared(smem);

    int tid  = threadIdx.x;
    int wid  = tid >> 5;
    int lane = tid & 31;
    int g    = lane >> 2;
    int tig  = lane & 3;
    int wm   = wid & 1;
    int wn   = wid >> 1;
    int kz   = blockIdx.z;

    const __half* Ab = A  + (size_t)kz * saz + (size_t)blockIdx.y * BM * Kd;
    const __half* Bb = Bt + (size_t)kz * sbz + (size_t)blockIdx.x * BN * Kd;
    OutT* Cb = C + (size_t)kz * scz;
    int KT = Kd / BK;

    float acc[4][8][4];
#pragma unroll
    for (int i = 0; i < 4; i++)
#pragma unroll
        for (int j = 0; j < 8; j++)
#pragma unroll
            for (int q = 0; q < 4; q++) acc[i][j][q] = 0.f;

    uint32_t xm      = (uint32_t)(lane & 7) << 4;
    uint32_t a_row   = (uint32_t)(wm * 64 + (lane & 15)) * 128;
    uint32_t a_klane = (uint32_t)((lane >> 1) & 8) * 2;
    int nlo          = (lane & 7) | ((lane & 16) >> 1);
    uint32_t b_klane = (uint32_t)(lane & 8) * 2;

    auto load_stage = [&](int stage, int kt) {
        uint32_t abase = sbase + stage * STAGEB;
        uint32_t bbase = abase + TILEB;
        const __half* As = Ab + (size_t)kt * BK;
        const __half* Bs = Bb + (size_t)kt * BK;
#pragma unroll
        for (int i = 0; i < 8; i++) {
            int c   = tid + NT * i;
            int row = c >> 3;
            int ch  = c & 7;
            uint32_t off = (uint32_t)row * 128 + (uint32_t)ch * 16;
            uint32_t sw  = off ^ ((off >> 3) & 0x70);
            cp16(abase + sw, As + (size_t)row * Kd + ch * 8);
            cp16(bbase + sw, Bs + (size_t)row * Kd + ch * 8);
        }
    };

#pragma unroll
    for (int s = 0; s < STAGES - 1; s++) {
        if (s < KT) load_stage(s, s);
        cp_commit();
    }

    for (int kt = 0; kt < KT; kt++) {
        cp_wait<STAGES - 2>();
        __syncthreads();

        int nxt = kt + STAGES - 1;
        if (nxt < KT) load_stage(nxt % STAGES, nxt);
        cp_commit();

        uint32_t abase = sbase + (kt % STAGES) * STAGEB;
        uint32_t bbase = abase + TILEB;

#pragma unroll
        for (int ks = 0; ks < 4; ks++) {
            uint32_t kb = (uint32_t)ks * 32;
            uint32_t af[4][4];
#pragma unroll
            for (int mf = 0; mf < 4; mf++)
                ldsm4(af[mf], abase + a_row + (uint32_t)mf * 16 * 128 +
                                ((kb + a_klane) ^ xm));
            uint32_t bf[4][4];
#pragma unroll
            for (int ng = 0; ng < 4; ng++)
                ldsm4(bf[ng], bbase + (uint32_t)(wn * 64 + ng * 16 + nlo) * 128 +
                                ((kb + b_klane) ^ xm));
#pragma unroll
            for (int mf = 0; mf < 4; mf++)
#pragma unroll
                for (int ng = 0; ng < 4; ng++) {
                    mma16816(acc[mf][2 * ng + 0], af[mf], &bf[ng][0]);
                    mma16816(acc[mf][2 * ng + 1], af[mf], &bf[ng][2]);
                }
        }
    }

    // ---- epilogue ----
#pragma unroll
    for (int mf = 0; mf < 4; mf++) {
        int row0 = blockIdx.y * BM + wm * 64 + mf * 16 + g;
#pragma unroll
        for (int half = 0; half < 2; half++) {
            int row = row0 + half * 8;
            float rs = 1.f;
            if (EPI == 2) rs = g_probs[row * KPATH + kz];
            if (EPI == 3) rs = pw[kz * HD + row];
            OutT* Crow = Cb + (size_t)row * N;
#pragma unroll
            for (int nf = 0; nf < 8; nf++) {
                int col = blockIdx.x * BN + wn * 64 + (nf >> 1) * 16 + (nf & 1) * 8 + 2 * tig;
                float v0 = acc[mf][nf][half * 2 + 0];
                float v1 = acc[mf][nf][half * 2 + 1];
                if (EPI == 1) { v0 = gelu_f(v0); v1 = gelu_f(v1); }
                if (EPI == 2 || EPI == 3) { v0 *= rs; v1 *= rs; }
                if (sizeof(OutT) == 2) {
                    __half2 hv = __floats2half2_rn(v0, v1);
                    *(__half2*)((__half*)Crow + col) = hv;
                } else {
                    *(float2*)((float*)Crow + col) = make_float2(v0, v1);
                }
            }
        }
    }
}

// ---------------- launch -----------------------------------------------------
extern "C" void kernel_launch(void* const* d_in, const int* in_sizes, int n_in,
                              void* d_out, int out_size)
{
    const float* x      = (const float*)d_in[0];
    const float* c1a    = (const float*)d_in[1];
    const float* c1b    = (const float*)d_in[2];
    const float* c2a    = (const float*)d_in[3];
    const float* c2b    = (const float*)d_in[4];
    const float* hd_in  = (const float*)d_in[5];
    const float* hd_out = (const float*)d_in[6];
    const float* pb     = (const float*)d_in[7];
    const float* pw     = (const float*)d_in[8];
    float* out = (float*)d_out;

    __half *W1h, *W2n, *Wfh, *hdinTh, *hdoutTh, *xh, *h4, *colh;
    float *col4;
    cudaGetSymbolAddress((void**)&W1h,     g_W1h);
    cudaGetSymbolAddress((void**)&W2n,     g_W2n);
    cudaGetSymbolAddress((void**)&Wfh,     g_Wfh);
    cudaGetSymbolAddress((void**)&hdinTh,  g_hdinTh);
    cudaGetSymbolAddress((void**)&hdoutTh, g_hdoutTh);
    cudaGetSymbolAddress((void**)&xh,      g_xh);
    cudaGetSymbolAddress((void**)&h4,      g_h4);
    cudaGetSymbolAddress((void**)&colh,    g_colh);
    cudaGetSymbolAddress((void**)&col4,    g_col4);

    static cudaStream_t s1 = nullptr;
    static cudaEvent_t e_fork = nullptr, e_prep = nullptr, e_wf = nullptr;
    static bool attr_set = false;
    if (!attr_set) {
        cudaFuncSetAttribute(tgemm<0, float>,  cudaFuncAttributeMaxDynamicSharedMemorySize, GEMM_SMEM);
        cudaFuncSetAttribute(tgemm<1, __half>, cudaFuncAttributeMaxDynamicSharedMemorySize, GEMM_SMEM);
        cudaFuncSetAttribute(tgemm<2, float>,  cudaFuncAttributeMaxDynamicSharedMemorySize, GEMM_SMEM);
        cudaFuncSetAttribute(tgemm<3, __half>, cudaFuncAttributeMaxDynamicSharedMemorySize, GEMM_SMEM);
        cudaStreamCreateWithFlags(&s1, cudaStreamNonBlocking);
        cudaEventCreateWithFlags(&e_fork, cudaEventDisableTiming);
        cudaEventCreateWithFlags(&e_prep, cudaEventDisableTiming);
        cudaEventCreateWithFlags(&e_wf,   cudaEventDisableTiming);
        attr_set = true;
    }

    // ---- fork side stream s1 into the (captured) main stream's graph ----
    cudaEventRecord(e_fork, 0);
    cudaStreamWaitEvent(s1, e_fork, 0);

    // s1: W2n -> S -> routing (independent of GEMM1's inputs)
    build_w2n<<<dim3(64, KPATH), 512, 0, s1>>>(c2a, c2b);
    build_S<<<(DMODEL * 32 + 255) / 256, 256, 0, s1>>>(hd_in, pb);
    routing_kernel<<<(BATCH * 32 + 255) / 256, 256, 0, s1>>>(x);

    // main stream: W1h, prep (xh / hdinTh / hdoutTh)
    build_w1h<<<dim3(64, KPATH), 512>>>(c1a, c1b);
    prep<<<2048, 256>>>(x, hd_in, hd_out);
    cudaEventRecord(e_prep, 0);
    cudaStreamWaitEvent(s1, e_prep, 0);    // Wf needs hdinTh from prep

    // s1: folded tail weights WfT_k[512,4096] = (hd_inT @ W2_k^T) * pw_k(row)
    tgemm<3, __half><<<dim3(DFF / BN, HD / BM, KPATH), NT, GEMM_SMEM, s1>>>(
        hdinTh, W2n, Wfh, HD, DFF, DMODEL, pw,
        0, (size_t)DFF * DMODEL, (size_t)HD * DFF);
    cudaEventRecord(e_wf, s1);

    // main: GEMM1 h_k = gelu(x @ W1_k) — overlaps the s1 chain
    tgemm<1, __half><<<dim3(DFF / BN, BATCH / BM, KPATH), NT, GEMM_SMEM>>>(
        xh, W1h, h4, BATCH, DFF, DMODEL, nullptr,
        0, (size_t)DFF * DMODEL, (size_t)BATCH * DFF);

    // join: tail needs h4 (main) + Wfh, probs (s1)
    cudaStreamWaitEvent(0, e_wf, 0);

    // main: col4_k = probs[:,k] * (h_k @ Wf_k)
    tgemm<2, float><<<dim3(HD / BN, BATCH / BM, KPATH), NT, GEMM_SMEM>>>(
        h4, Wfh, col4, BATCH, HD, DFF, nullptr,
        (size_t)BATCH * DFF, (size_t)HD * DFF, (size_t)BATCH * HD);

    // main: reduce partials -> colh (fp16)
    reduce_col<<<(BATCH * HD + 255) / 256, 256>>>();

    // main: out = col @ hd_out (fp32)
    tgemm<0, float><<<dim3(DMODEL / BN, BATCH / BM, 1), NT, GEMM_SMEM>>>(
        colh, hdoutTh, out, BATCH, DMODEL, HD, nullptr, 0, 0, 0);
}